// round 7
// baseline (speedup 1.0000x reference)
#include <cuda_runtime.h>
#include <cstdint>

#define NN  40000
#define EE  640000
#define NNZ (EE + NN)   // 680000 (edges + self-loops)

#define NSCAN_BLK 40    // 40 blocks x 1000 elements = NN
#define SCAN_CH   1000

typedef unsigned long long ull;

// ---------------- scratch (device globals — no runtime allocation) ----------
__device__ __align__(256) float g_buf0[NN * 128];
__device__ __align__(256) float g_buf1[NN * 128];
__device__ float g_dinv[NN];
__device__ int   g_deg[NN];          // zero at load; scan re-zeroes after read
__device__ int   g_rowptr[NN + 1];
__device__ int   g_cursor[NN];
__device__ __align__(16) int2 g_adj[NNZ];   // {col, bitcast(weight)}
__device__ volatile int g_scan_flag[NSCAN_BLK];  // zero at load; consumer resets
__device__ volatile int g_scan_pref[NSCAN_BLK];

// ---------------- packed fp32x2 helpers (sm_10x) -----------------------------
__device__ __forceinline__ ull ffma2(ull a, ull b, ull c) {
  ull d;
  asm("fma.rn.f32x2 %0, %1, %2, %3;" : "=l"(d) : "l"(a), "l"(b), "l"(c));
  return d;
}
__device__ __forceinline__ float hsum2(ull v) {
  float lo, hi;
  asm("mov.b64 {%0, %1}, %2;" : "=f"(lo), "=f"(hi) : "l"(v));
  return lo + hi;
}
__device__ __forceinline__ ull pack2(float lo, float hi) {
  ull v;
  asm("mov.b64 %0, {%1, %2};" : "=l"(v) : "f"(lo), "f"(hi));
  return v;
}

// ---------------- preprocessing ---------------------------------------------
__global__ void count_deg_kernel(const int* __restrict__ dst) {
  int e = blockIdx.x * 256 + threadIdx.x;
  if (e < EE) atomicAdd(&g_deg[dst[e]], 1);
}

// One-kernel exclusive scan of (deg+1) via decoupled lookback (40 blocks,
// chained by blockIdx). Also computes dinv and re-zeroes g_deg (restores the
// pre-run invariant so the next replay's count_deg starts from zero).
__global__ void __launch_bounds__(256) scan_fused_kernel() {
  __shared__ int warp_pref[8];
  __shared__ int s_base;
  const int b = blockIdx.x, t = threadIdx.x;
  const int lane = t & 31, warp = t >> 5;

  int v[4];
  int s = 0;
#pragma unroll
  for (int i = 0; i < 4; i++) {
    int li = t * 4 + i;
    int d1 = 0;
    if (li < SCAN_CH) {
      int idx = b * SCAN_CH + li;
      d1 = g_deg[idx] + 1;
      g_deg[idx] = 0;
      g_dinv[idx] = rsqrtf((float)d1);
    }
    v[i] = s;       // exclusive within thread
    s += d1;
  }
  // inclusive warp scan of thread sums
  int ws = s;
#pragma unroll
  for (int off = 1; off < 32; off <<= 1) {
    int u = __shfl_up_sync(0xffffffffu, ws, off);
    if (lane >= off) ws += u;
  }
  if (lane == 31) warp_pref[warp] = ws;
  __syncthreads();
  if (t == 0) {
    int run = 0;
#pragma unroll
    for (int i = 0; i < 8; i++) { int x = warp_pref[i]; warp_pref[i] = run; run += x; }
    // lookback
    int pref = 0;
    if (b > 0) {
      while (g_scan_flag[b - 1] == 0) {}
      __threadfence();
      pref = g_scan_pref[b - 1];
      g_scan_flag[b - 1] = 0;   // single consumer: restore for next replay
    }
    if (b < NSCAN_BLK - 1) {
      g_scan_pref[b] = pref + run;
      __threadfence();
      g_scan_flag[b] = 1;
    } else {
      g_rowptr[NN] = pref + run;
    }
    s_base = pref;
  }
  __syncthreads();
  const int base = s_base + warp_pref[warp] + (ws - s);
#pragma unroll
  for (int i = 0; i < 4; i++) {
    int li = t * 4 + i;
    if (li < SCAN_CH) {
      int idx = b * SCAN_CH + li;
      int p = base + v[i];
      g_rowptr[idx] = p;
      g_cursor[idx] = p;
    }
  }
}

__global__ void fill_csr_kernel(const int* __restrict__ src,
                                const int* __restrict__ dst) {
  int t = blockIdx.x * 256 + threadIdx.x;
  if (t < EE) {
    int s = src[t], d = dst[t];
    int pos = atomicAdd(&g_cursor[d], 1);
    g_adj[pos] = make_int2(s, __float_as_int(g_dinv[s] * g_dinv[d]));
  } else if (t < NNZ) {
    int i = t - EE;
    int pos = atomicAdd(&g_cursor[i], 1);
    float di = g_dinv[i];
    g_adj[pos] = make_int2(i, __float_as_int(di * di));
  }
}

// ---------------- shared row-aggregation primitive ---------------------------
// Returns sum_{e in row(node)} w[e] * Hin[col[e]][sub*4 .. sub*4+3].
// Unroll 8 edges/iter; adjacency via int4 (2 edges / 16B load).
#define AGG_ONE(cx, wy)                                                        \
  {                                                                            \
    float4 xx = __ldg(reinterpret_cast<const float4*>(Hin + (size_t)(cx) * D) + sub); \
    ull ww = pack2(__int_as_float(wy), __int_as_float(wy));                    \
    a01 = ffma2(reinterpret_cast<ull*>(&xx)[0], ww, a01);                      \
    a23 = ffma2(reinterpret_cast<ull*>(&xx)[1], ww, a23);                      \
  }

template <int D>
__device__ __forceinline__ float4 agg_row(const float* __restrict__ Hin,
                                          int node, int sub) {
  int e = g_rowptr[node];
  const int end = g_rowptr[node + 1];
  ull a01 = 0ull, a23 = 0ull;
  if ((e & 1) && e < end) {   // align to even index for int4 adjacency loads
    int2 av = __ldg(&g_adj[e]);
    AGG_ONE(av.x, av.y);
    e++;
  }
  for (; e + 8 <= end; e += 8) {
    int4 q0 = __ldg(reinterpret_cast<const int4*>(g_adj + e));
    int4 q1 = __ldg(reinterpret_cast<const int4*>(g_adj + e + 2));
    int4 q2 = __ldg(reinterpret_cast<const int4*>(g_adj + e + 4));
    int4 q3 = __ldg(reinterpret_cast<const int4*>(g_adj + e + 6));
    float4 x0 = __ldg(reinterpret_cast<const float4*>(Hin + (size_t)q0.x * D) + sub);
    float4 x1 = __ldg(reinterpret_cast<const float4*>(Hin + (size_t)q0.z * D) + sub);
    float4 x2 = __ldg(reinterpret_cast<const float4*>(Hin + (size_t)q1.x * D) + sub);
    float4 x3 = __ldg(reinterpret_cast<const float4*>(Hin + (size_t)q1.z * D) + sub);
    float4 x4 = __ldg(reinterpret_cast<const float4*>(Hin + (size_t)q2.x * D) + sub);
    float4 x5 = __ldg(reinterpret_cast<const float4*>(Hin + (size_t)q2.z * D) + sub);
    float4 x6 = __ldg(reinterpret_cast<const float4*>(Hin + (size_t)q3.x * D) + sub);
    float4 x7 = __ldg(reinterpret_cast<const float4*>(Hin + (size_t)q3.z * D) + sub);
    ull w0 = pack2(__int_as_float(q0.y), __int_as_float(q0.y));
    ull w1 = pack2(__int_as_float(q0.w), __int_as_float(q0.w));
    ull w2 = pack2(__int_as_float(q1.y), __int_as_float(q1.y));
    ull w3 = pack2(__int_as_float(q1.w), __int_as_float(q1.w));
    ull w4 = pack2(__int_as_float(q2.y), __int_as_float(q2.y));
    ull w5 = pack2(__int_as_float(q2.w), __int_as_float(q2.w));
    ull w6 = pack2(__int_as_float(q3.y), __int_as_float(q3.y));
    ull w7 = pack2(__int_as_float(q3.w), __int_as_float(q3.w));
    a01 = ffma2(reinterpret_cast<ull*>(&x0)[0], w0, a01);
    a23 = ffma2(reinterpret_cast<ull*>(&x0)[1], w0, a23);
    a01 = ffma2(reinterpret_cast<ull*>(&x1)[0], w1, a01);
    a23 = ffma2(reinterpret_cast<ull*>(&x1)[1], w1, a23);
    a01 = ffma2(reinterpret_cast<ull*>(&x2)[0], w2, a01);
    a23 = ffma2(reinterpret_cast<ull*>(&x2)[1], w2, a23);
    a01 = ffma2(reinterpret_cast<ull*>(&x3)[0], w3, a01);
    a23 = ffma2(reinterpret_cast<ull*>(&x3)[1], w3, a23);
    a01 = ffma2(reinterpret_cast<ull*>(&x4)[0], w4, a01);
    a23 = ffma2(reinterpret_cast<ull*>(&x4)[1], w4, a23);
    a01 = ffma2(reinterpret_cast<ull*>(&x5)[0], w5, a01);
    a23 = ffma2(reinterpret_cast<ull*>(&x5)[1], w5, a23);
    a01 = ffma2(reinterpret_cast<ull*>(&x6)[0], w6, a01);
    a23 = ffma2(reinterpret_cast<ull*>(&x6)[1], w6, a23);
    a01 = ffma2(reinterpret_cast<ull*>(&x7)[0], w7, a01);
    a23 = ffma2(reinterpret_cast<ull*>(&x7)[1], w7, a23);
  }
  for (; e + 2 <= end; e += 2) {
    int4 q = __ldg(reinterpret_cast<const int4*>(g_adj + e));
    AGG_ONE(q.x, q.y);
    AGG_ONE(q.z, q.w);
  }
  if (e < end) {
    int2 av = __ldg(&g_adj[e]);
    AGG_ONE(av.x, av.y);
  }
  float4 r;
  r.x = __int_as_float((int)(a01 & 0xffffffffull));
  r.y = __int_as_float((int)(a01 >> 32));
  r.z = __int_as_float((int)(a23 & 0xffffffffull));
  r.w = __int_as_float((int)(a23 >> 32));
  return r;
}
#undef AGG_ONE

__device__ __forceinline__ float4 bias_relu4(float4 a, const float* bias,
                                             int sub, bool do_bias, bool do_relu) {
  if (do_bias) {
    float4 b = __ldg(reinterpret_cast<const float4*>(bias) + sub);
    a.x += b.x; a.y += b.y; a.z += b.z; a.w += b.w;
  }
  if (do_relu) {
    a.x = fmaxf(a.x, 0.f); a.y = fmaxf(a.y, 0.f);
    a.z = fmaxf(a.z, 0.f); a.w = fmaxf(a.w, 0.f);
  }
  return a;
}

// ---------------- standalone aggregation kernels -----------------------------
template <bool RELU, bool BIAS>
__global__ void __launch_bounds__(256) agg64_kernel(
    const float* __restrict__ Hin, const float* __restrict__ bias,
    float* __restrict__ Hout) {
  const int node = blockIdx.x * 16 + (threadIdx.x >> 4);
  const int sub = threadIdx.x & 15;
  float4 acc = agg_row<64>(Hin, node, sub);
  acc = bias_relu4(acc, bias, sub, BIAS, RELU);
  reinterpret_cast<float4*>(Hout + (size_t)node * 64)[sub] = acc;
}

template <bool RELU, bool BIAS>
__global__ void __launch_bounds__(256) agg128_kernel(
    const float* __restrict__ Hin, const float* __restrict__ bias,
    float* __restrict__ Hout) {
  const int node = blockIdx.x * 8 + (threadIdx.x >> 5);
  const int sub = threadIdx.x & 31;
  float4 acc = agg_row<128>(Hin, node, sub);
  acc = bias_relu4(acc, bias, sub, BIAS, RELU);
  reinterpret_cast<float4*>(Hout + (size_t)node * 128)[sub] = acc;
}

// ---------------- dense: out[N,DOUT] = A[N,K] @ W[K,DOUT] (+bias)(relu) -----
template <int K, int DOUT, bool RELU, bool BIAS>
__global__ void __launch_bounds__(256) gemm_kernel(
    const float* __restrict__ A, const float* __restrict__ W,
    const float* __restrict__ bias, float* __restrict__ out) {
  constexpr int COLT = (DOUT < 64) ? DOUT : 64;
  constexpr int VPT = COLT / 32;   // 1 or 2
  constexpr int KS = K + 4;        // padded stride (words)
  constexpr int R = 8;
  __shared__ __align__(16) float Ws[COLT * KS];

  const int col0 = blockIdx.y * COLT;
  for (int i = threadIdx.x; i < COLT * K; i += 256) {
    int c = i / K, k = i - c * K;
    Ws[c * KS + k] = W[k * DOUT + col0 + c];
  }
  __syncthreads();

  const int lane = threadIdx.x & 31;
  const int row0 = (blockIdx.x * 8 + (threadIdx.x >> 5)) * R;

  ull acc[R][VPT];
#pragma unroll
  for (int r = 0; r < R; r++)
#pragma unroll
    for (int v = 0; v < VPT; v++) acc[r][v] = 0ull;

  const float* a_base = A + (size_t)row0 * K;
#pragma unroll 2
  for (int k = 0; k < K; k += 4) {
    ull w01[VPT], w23[VPT];
#pragma unroll
    for (int v = 0; v < VPT; v++) {
      float4 wv = *reinterpret_cast<const float4*>(&Ws[(lane + 32 * v) * KS + k]);
      w01[v] = reinterpret_cast<ull*>(&wv)[0];
      w23[v] = reinterpret_cast<ull*>(&wv)[1];
    }
#pragma unroll
    for (int r = 0; r < R; r++) {
      float4 av = __ldg(reinterpret_cast<const float4*>(a_base + r * K + k));
      ull a01 = reinterpret_cast<ull*>(&av)[0];
      ull a23 = reinterpret_cast<ull*>(&av)[1];
#pragma unroll
      for (int v = 0; v < VPT; v++) {
        acc[r][v] = ffma2(a01, w01[v], acc[r][v]);
        acc[r][v] = ffma2(a23, w23[v], acc[r][v]);
      }
    }
  }

#pragma unroll
  for (int r = 0; r < R; r++) {
#pragma unroll
    for (int v = 0; v < VPT; v++) {
      float s = hsum2(acc[r][v]);
      int c = col0 + lane + 32 * v;
      if (BIAS) s += __ldg(&bias[c]);
      if (RELU) s = fmaxf(s, 0.0f);
      out[(size_t)(row0 + r) * DOUT + c] = s;
    }
  }
}

// ---------------- fused agg128 -> gemm(128->64) ------------------------------
// h3 = relu(agg(t3) + b3) built in shared, then t4 = h3 @ W4.
#define FA_KS 132
__global__ void __launch_bounds__(256) fused_agg128_gemm64_kernel(
    const float* __restrict__ Hin, const float* __restrict__ aggbias,
    const float* __restrict__ W, float* __restrict__ out) {
  extern __shared__ __align__(16) float sm[];
  float* As = sm;                    // [64][FA_KS]
  float* Ws = sm + 64 * FA_KS;       // [64][FA_KS] : Ws[c][k] = W[k][c]

  const int tid = threadIdx.x;
  const int lane = tid & 31;
  const int warp = tid >> 5;
  const int row0 = blockIdx.x * 64;

  for (int i = tid; i < 64 * 128; i += 256) {
    int c = i >> 7, k = i & 127;
    Ws[c * FA_KS + k] = W[k * 64 + c];
  }
  // phase A: each warp aggregates 8 rows (full warp per row, D=128)
#pragma unroll 2
  for (int r = 0; r < 8; r++) {
    int lrow = warp * 8 + r;
    float4 v = agg_row<128>(Hin, row0 + lrow, lane);
    v = bias_relu4(v, aggbias, lane, true, true);
    *reinterpret_cast<float4*>(&As[lrow * FA_KS + lane * 4]) = v;
  }
  __syncthreads();

  // phase B: gemm K=128 -> 64 cols (VPT=2), R=8 rows/warp, A from shared
  ull acc[8][2];
#pragma unroll
  for (int r = 0; r < 8; r++) { acc[r][0] = 0ull; acc[r][1] = 0ull; }
#pragma unroll 2
  for (int k = 0; k < 128; k += 4) {
    ull w01[2], w23[2];
#pragma unroll
    for (int v = 0; v < 2; v++) {
      float4 wv = *reinterpret_cast<const float4*>(&Ws[(lane + 32 * v) * FA_KS + k]);
      w01[v] = reinterpret_cast<ull*>(&wv)[0];
      w23[v] = reinterpret_cast<ull*>(&wv)[1];
    }
#pragma unroll
    for (int r = 0; r < 8; r++) {
      float4 av = *reinterpret_cast<const float4*>(&As[(warp * 8 + r) * FA_KS + k]);
      ull a01 = reinterpret_cast<ull*>(&av)[0];
      ull a23 = reinterpret_cast<ull*>(&av)[1];
#pragma unroll
      for (int v = 0; v < 2; v++) {
        acc[r][v] = ffma2(a01, w01[v], acc[r][v]);
        acc[r][v] = ffma2(a23, w23[v], acc[r][v]);
      }
    }
  }
#pragma unroll
  for (int r = 0; r < 8; r++)
#pragma unroll
    for (int v = 0; v < 2; v++)
      out[(size_t)(row0 + warp * 8 + r) * 64 + lane + 32 * v] = hsum2(acc[r][v]);
}
#define FA128_SMEM (2 * 64 * FA_KS * 4)   // 67584 bytes

// ---------------- fused agg64 -> gemm(64->32)+bias ---------------------------
// h4 = relu(agg(t4) + b4) built in shared, then out = h4 @ Wl + bl.
#define FB_KS 68
__global__ void __launch_bounds__(256) fused_agg64_gemm32_kernel(
    const float* __restrict__ Hin, const float* __restrict__ aggbias,
    const float* __restrict__ W, const float* __restrict__ bias,
    float* __restrict__ out) {
  __shared__ __align__(16) float As[64 * FB_KS];
  __shared__ __align__(16) float Ws[32 * FB_KS];

  const int tid = threadIdx.x;
  const int lane = tid & 31;
  const int warp = tid >> 5;
  const int row0 = blockIdx.x * 64;

  for (int i = tid; i < 32 * 64; i += 256) {
    int c = i >> 6, k = i & 63;
    Ws[c * FB_KS + k] = W[k * 32 + c];
  }
  // phase A: half-warp per row, 4 rows per half-warp (D=64)
  {
    const int hw = tid >> 4;
    const int sub = tid & 15;
#pragma unroll
    for (int r = 0; r < 4; r++) {
      int lrow = hw * 4 + r;
      float4 v = agg_row<64>(Hin, row0 + lrow, sub);
      v = bias_relu4(v, aggbias, sub, true, true);
      *reinterpret_cast<float4*>(&As[lrow * FB_KS + sub * 4]) = v;
    }
  }
  __syncthreads();

  // phase B: gemm K=64 -> 32 cols (VPT=1), R=8 rows/warp
  ull acc[8];
#pragma unroll
  for (int r = 0; r < 8; r++) acc[r] = 0ull;
#pragma unroll 2
  for (int k = 0; k < 64; k += 4) {
    float4 wv = *reinterpret_cast<const float4*>(&Ws[lane * FB_KS + k]);
    ull w01 = reinterpret_cast<ull*>(&wv)[0];
    ull w23 = reinterpret_cast<ull*>(&wv)[1];
#pragma unroll
    for (int r = 0; r < 8; r++) {
      float4 av = *reinterpret_cast<const float4*>(&As[(warp * 8 + r) * FB_KS + k]);
      acc[r] = ffma2(reinterpret_cast<ull*>(&av)[0], w01, acc[r]);
      acc[r] = ffma2(reinterpret_cast<ull*>(&av)[1], w23, acc[r]);
    }
  }
  const float bl = __ldg(&bias[lane]);
#pragma unroll
  for (int r = 0; r < 8; r++)
    out[(size_t)(row0 + warp * 8 + r) * 32 + lane] = hsum2(acc[r]) + bl;
}

// ---------------- launch ------------------------------------------------------
extern "C" void kernel_launch(void* const* d_in, const int* in_sizes, int n_in,
                              void* d_out, int out_size) {
  (void)in_sizes; (void)n_in; (void)out_size;
  const float* x  = (const float*)d_in[0];
  const int*   ei = (const int*)d_in[1];
  const int* src = ei;
  const int* dst = ei + EE;
  const float* W1 = (const float*)d_in[3];
  const float* b1 = (const float*)d_in[4];
  const float* W2 = (const float*)d_in[5];
  const float* b2 = (const float*)d_in[6];
  const float* W3 = (const float*)d_in[7];
  const float* b3 = (const float*)d_in[8];
  const float* W4 = (const float*)d_in[9];
  const float* b4 = (const float*)d_in[10];
  const float* Wl = (const float*)d_in[11];
  const float* bl = (const float*)d_in[12];
  float* out = (float*)d_out;

  float *buf0, *buf1;
  cudaGetSymbolAddress((void**)&buf0, g_buf0);
  cudaGetSymbolAddress((void**)&buf1, g_buf1);

  // One-time infra (host objects only; no device allocation).
  static cudaStream_t s_prep = nullptr;
  static cudaEvent_t ev_fork = nullptr, ev_join = nullptr;
  if (s_prep == nullptr) {
    cudaStreamCreateWithFlags(&s_prep, cudaStreamNonBlocking);
    cudaEventCreateWithFlags(&ev_fork, cudaEventDisableTiming);
    cudaEventCreateWithFlags(&ev_join, cudaEventDisableTiming);
    cudaFuncSetAttribute(fused_agg128_gemm64_kernel,
                         cudaFuncAttributeMaxDynamicSharedMemorySize, FA128_SMEM);
  }

  // ---- fork: CSR prep (depends only on edge_index) on s_prep, concurrent
  //      with gemm1 (depends only on x, W1) on the main stream.
  cudaEventRecord(ev_fork, 0);
  cudaStreamWaitEvent(s_prep, ev_fork, 0);

  count_deg_kernel<<<(EE + 255) / 256, 256, 0, s_prep>>>(dst);
  scan_fused_kernel<<<NSCAN_BLK, 256, 0, s_prep>>>();
  fill_csr_kernel<<<(NNZ + 255) / 256, 256, 0, s_prep>>>(src, dst);
  cudaEventRecord(ev_join, s_prep);

  const int GEMM_BLOCKS = NN / 64;    // 625
  const int AGG64_BLOCKS = NN / 16;   // 2500 (half-warp per node)

  // L1 GEMM overlaps prep: t = x @ W1
  gemm_kernel<128, 64, false, false><<<dim3(GEMM_BLOCKS, 1), 256>>>(x, W1, nullptr, buf0);

  cudaStreamWaitEvent(0, ev_join, 0);  // join: aggs need the CSR

  // h1 = relu(agg(t) + b1)
  agg64_kernel<true, true><<<AGG64_BLOCKS, 256>>>(buf0, b1, buf1);
  // L2 agg-first: a = agg(h1)
  agg64_kernel<false, false><<<AGG64_BLOCKS, 256>>>(buf1, nullptr, buf0);
  // h2 = relu(a @ W2 + b2)
  gemm_kernel<64, 128, true, true><<<dim3(GEMM_BLOCKS, 2), 256>>>(buf0, W2, b2, buf1);
  // t3 = h2 @ W3
  gemm_kernel<128, 128, false, false><<<dim3(GEMM_BLOCKS, 2), 256>>>(buf1, W3, nullptr, buf0);
  // fused: h3 = relu(agg(t3)+b3) ; t4 = h3 @ W4
  fused_agg128_gemm64_kernel<<<GEMM_BLOCKS, 256, FA128_SMEM>>>(buf0, b3, W4, buf1);
  // fused: h4 = relu(agg(t4)+b4) ; out = h4 @ Wl + bl
  fused_agg64_gemm32_kernel<<<GEMM_BLOCKS, 256>>>(buf1, b4, Wl, bl, out);
}

// round 8
// speedup vs baseline: 1.1254x; 1.1254x over previous
#include <cuda_runtime.h>
#include <cstdint>

#define NN  40000
#define EE  640000
#define NNZ (EE + NN)   // 680000 (edges + self-loops)

#define NSCAN_BLK 40    // 40 blocks x 1000 elements = NN
#define SCAN_CH   1000

typedef unsigned long long ull;

// ---------------- scratch (device globals — no runtime allocation) ----------
__device__ __align__(256) float g_buf0[NN * 128];
__device__ __align__(256) float g_buf1[NN * 128];
__device__ float g_dinv[NN];
__device__ int   g_deg[NN];          // zero at load; scan re-zeroes after read
__device__ int   g_rowptr[NN + 1];
__device__ int   g_cursor[NN];
__device__ __align__(16) int2 g_adj[NNZ];   // {col, bitcast(weight)}
__device__ volatile int g_scan_flag[NSCAN_BLK];  // zero at load; consumer resets
__device__ volatile int g_scan_pref[NSCAN_BLK];

// ---------------- packed fp32x2 helpers (sm_10x) -----------------------------
__device__ __forceinline__ ull ffma2(ull a, ull b, ull c) {
  ull d;
  asm("fma.rn.f32x2 %0, %1, %2, %3;" : "=l"(d) : "l"(a), "l"(b), "l"(c));
  return d;
}
__device__ __forceinline__ float hsum2(ull v) {
  float lo, hi;
  asm("mov.b64 {%0, %1}, %2;" : "=f"(lo), "=f"(hi) : "l"(v));
  return lo + hi;
}
__device__ __forceinline__ ull pack2(float lo, float hi) {
  ull v;
  asm("mov.b64 %0, {%1, %2};" : "=l"(v) : "f"(lo), "f"(hi));
  return v;
}
__device__ __forceinline__ void cp_async16(uint32_t saddr, const void* gaddr) {
  asm volatile("cp.async.cg.shared.global [%0], [%1], 16;\n"
               :: "r"(saddr), "l"(gaddr));
}

// ---------------- preprocessing ---------------------------------------------
__global__ void count_deg_kernel(const int* __restrict__ dst) {
  int e = blockIdx.x * 256 + threadIdx.x;
  if (e < EE) atomicAdd(&g_deg[dst[e]], 1);
}

// One-kernel exclusive scan of (deg+1) via decoupled lookback. Also computes
// dinv and re-zeroes g_deg (restores the pre-run invariant for replays).
__global__ void __launch_bounds__(256) scan_fused_kernel() {
  __shared__ int warp_pref[8];
  __shared__ int s_base;
  const int b = blockIdx.x, t = threadIdx.x;
  const int lane = t & 31, warp = t >> 5;

  int v[4];
  int s = 0;
#pragma unroll
  for (int i = 0; i < 4; i++) {
    int li = t * 4 + i;
    int d1 = 0;
    if (li < SCAN_CH) {
      int idx = b * SCAN_CH + li;
      d1 = g_deg[idx] + 1;
      g_deg[idx] = 0;
      g_dinv[idx] = rsqrtf((float)d1);
    }
    v[i] = s;
    s += d1;
  }
  int ws = s;
#pragma unroll
  for (int off = 1; off < 32; off <<= 1) {
    int u = __shfl_up_sync(0xffffffffu, ws, off);
    if (lane >= off) ws += u;
  }
  if (lane == 31) warp_pref[warp] = ws;
  __syncthreads();
  if (t == 0) {
    int run = 0;
#pragma unroll
    for (int i = 0; i < 8; i++) { int x = warp_pref[i]; warp_pref[i] = run; run += x; }
    int pref = 0;
    if (b > 0) {
      while (g_scan_flag[b - 1] == 0) {}
      __threadfence();
      pref = g_scan_pref[b - 1];
      g_scan_flag[b - 1] = 0;
    }
    if (b < NSCAN_BLK - 1) {
      g_scan_pref[b] = pref + run;
      __threadfence();
      g_scan_flag[b] = 1;
    } else {
      g_rowptr[NN] = pref + run;
    }
    s_base = pref;
  }
  __syncthreads();
  const int base = s_base + warp_pref[warp] + (ws - s);
#pragma unroll
  for (int i = 0; i < 4; i++) {
    int li = t * 4 + i;
    if (li < SCAN_CH) {
      int idx = b * SCAN_CH + li;
      int p = base + v[i];
      g_rowptr[idx] = p;
      g_cursor[idx] = p;
    }
  }
}

__global__ void fill_csr_kernel(const int* __restrict__ src,
                                const int* __restrict__ dst) {
  int t = blockIdx.x * 256 + threadIdx.x;
  if (t < EE) {
    int s = src[t], d = dst[t];
    int pos = atomicAdd(&g_cursor[d], 1);
    g_adj[pos] = make_int2(s, __float_as_int(g_dinv[s] * g_dinv[d]));
  } else if (t < NNZ) {
    int i = t - EE;
    int pos = atomicAdd(&g_cursor[i], 1);
    float di = g_dinv[i];
    g_adj[pos] = make_int2(i, __float_as_int(di * di));
  }
}

// ---------------- shared row-aggregation primitive ---------------------------
#define AGG_ONE(cx, wy)                                                        \
  {                                                                            \
    float4 xx = __ldg(reinterpret_cast<const float4*>(Hin + (size_t)(cx) * D) + sub); \
    ull ww = pack2(__int_as_float(wy), __int_as_float(wy));                    \
    a01 = ffma2(reinterpret_cast<ull*>(&xx)[0], ww, a01);                      \
    a23 = ffma2(reinterpret_cast<ull*>(&xx)[1], ww, a23);                      \
  }

template <int D>
__device__ __forceinline__ float4 agg_row(const float* __restrict__ Hin,
                                          int node, int sub) {
  int e = g_rowptr[node];
  const int end = g_rowptr[node + 1];
  ull a01 = 0ull, a23 = 0ull;
  if ((e & 1) && e < end) {
    int2 av = __ldg(&g_adj[e]);
    AGG_ONE(av.x, av.y);
    e++;
  }
  for (; e + 8 <= end; e += 8) {
    int4 q0 = __ldg(reinterpret_cast<const int4*>(g_adj + e));
    int4 q1 = __ldg(reinterpret_cast<const int4*>(g_adj + e + 2));
    int4 q2 = __ldg(reinterpret_cast<const int4*>(g_adj + e + 4));
    int4 q3 = __ldg(reinterpret_cast<const int4*>(g_adj + e + 6));
    float4 x0 = __ldg(reinterpret_cast<const float4*>(Hin + (size_t)q0.x * D) + sub);
    float4 x1 = __ldg(reinterpret_cast<const float4*>(Hin + (size_t)q0.z * D) + sub);
    float4 x2 = __ldg(reinterpret_cast<const float4*>(Hin + (size_t)q1.x * D) + sub);
    float4 x3 = __ldg(reinterpret_cast<const float4*>(Hin + (size_t)q1.z * D) + sub);
    float4 x4 = __ldg(reinterpret_cast<const float4*>(Hin + (size_t)q2.x * D) + sub);
    float4 x5 = __ldg(reinterpret_cast<const float4*>(Hin + (size_t)q2.z * D) + sub);
    float4 x6 = __ldg(reinterpret_cast<const float4*>(Hin + (size_t)q3.x * D) + sub);
    float4 x7 = __ldg(reinterpret_cast<const float4*>(Hin + (size_t)q3.z * D) + sub);
    ull w0 = pack2(__int_as_float(q0.y), __int_as_float(q0.y));
    ull w1 = pack2(__int_as_float(q0.w), __int_as_float(q0.w));
    ull w2 = pack2(__int_as_float(q1.y), __int_as_float(q1.y));
    ull w3 = pack2(__int_as_float(q1.w), __int_as_float(q1.w));
    ull w4 = pack2(__int_as_float(q2.y), __int_as_float(q2.y));
    ull w5 = pack2(__int_as_float(q2.w), __int_as_float(q2.w));
    ull w6 = pack2(__int_as_float(q3.y), __int_as_float(q3.y));
    ull w7 = pack2(__int_as_float(q3.w), __int_as_float(q3.w));
    a01 = ffma2(reinterpret_cast<ull*>(&x0)[0], w0, a01);
    a23 = ffma2(reinterpret_cast<ull*>(&x0)[1], w0, a23);
    a01 = ffma2(reinterpret_cast<ull*>(&x1)[0], w1, a01);
    a23 = ffma2(reinterpret_cast<ull*>(&x1)[1], w1, a23);
    a01 = ffma2(reinterpret_cast<ull*>(&x2)[0], w2, a01);
    a23 = ffma2(reinterpret_cast<ull*>(&x2)[1], w2, a23);
    a01 = ffma2(reinterpret_cast<ull*>(&x3)[0], w3, a01);
    a23 = ffma2(reinterpret_cast<ull*>(&x3)[1], w3, a23);
    a01 = ffma2(reinterpret_cast<ull*>(&x4)[0], w4, a01);
    a23 = ffma2(reinterpret_cast<ull*>(&x4)[1], w4, a23);
    a01 = ffma2(reinterpret_cast<ull*>(&x5)[0], w5, a01);
    a23 = ffma2(reinterpret_cast<ull*>(&x5)[1], w5, a23);
    a01 = ffma2(reinterpret_cast<ull*>(&x6)[0], w6, a01);
    a23 = ffma2(reinterpret_cast<ull*>(&x6)[1], w6, a23);
    a01 = ffma2(reinterpret_cast<ull*>(&x7)[0], w7, a01);
    a23 = ffma2(reinterpret_cast<ull*>(&x7)[1], w7, a23);
  }
  for (; e + 2 <= end; e += 2) {
    int4 q = __ldg(reinterpret_cast<const int4*>(g_adj + e));
    AGG_ONE(q.x, q.y);
    AGG_ONE(q.z, q.w);
  }
  if (e < end) {
    int2 av = __ldg(&g_adj[e]);
    AGG_ONE(av.x, av.y);
  }
  float4 r;
  r.x = __int_as_float((int)(a01 & 0xffffffffull));
  r.y = __int_as_float((int)(a01 >> 32));
  r.z = __int_as_float((int)(a23 & 0xffffffffull));
  r.w = __int_as_float((int)(a23 >> 32));
  return r;
}
#undef AGG_ONE

__device__ __forceinline__ float4 bias_relu4(float4 a, const float* bias,
                                             int sub, bool do_bias, bool do_relu) {
  if (do_bias) {
    float4 b = __ldg(reinterpret_cast<const float4*>(bias) + sub);
    a.x += b.x; a.y += b.y; a.z += b.z; a.w += b.w;
  }
  if (do_relu) {
    a.x = fmaxf(a.x, 0.f); a.y = fmaxf(a.y, 0.f);
    a.z = fmaxf(a.z, 0.f); a.w = fmaxf(a.w, 0.f);
  }
  return a;
}

// ---------------- standalone aggregation kernels -----------------------------
template <bool RELU, bool BIAS>
__global__ void __launch_bounds__(256) agg64_kernel(
    const float* __restrict__ Hin, const float* __restrict__ bias,
    float* __restrict__ Hout) {
  const int node = blockIdx.x * 16 + (threadIdx.x >> 4);
  const int sub = threadIdx.x & 15;
  float4 acc = agg_row<64>(Hin, node, sub);
  acc = bias_relu4(acc, bias, sub, BIAS, RELU);
  reinterpret_cast<float4*>(Hout + (size_t)node * 64)[sub] = acc;
}

template <bool RELU, bool BIAS>
__global__ void __launch_bounds__(256) agg128_kernel(
    const float* __restrict__ Hin, const float* __restrict__ bias,
    float* __restrict__ Hout) {
  const int node = blockIdx.x * 8 + (threadIdx.x >> 5);
  const int sub = threadIdx.x & 31;
  float4 acc = agg_row<128>(Hin, node, sub);
  acc = bias_relu4(acc, bias, sub, BIAS, RELU);
  reinterpret_cast<float4*>(Hout + (size_t)node * 128)[sub] = acc;
}

// ---------------- dense: out[N,DOUT] = A[N,K] @ W[K,DOUT] (+bias)(relu) -----
// A tile (64 rows) staged in shared via cp.async (one bulk issue per block ->
// single exposed DRAM latency, BW-limited thereafter). Compute reads A via
// LDS broadcast (uniform address per warp) and W via conflict-free LDS.128.
template <int K, int DOUT, bool RELU, bool BIAS>
__global__ void __launch_bounds__(256) gemm_kernel(
    const float* __restrict__ A, const float* __restrict__ W,
    const float* __restrict__ bias, float* __restrict__ out) {
  constexpr int COLT = (DOUT < 64) ? DOUT : 64;
  constexpr int VPT = COLT / 32;   // 1 or 2
  constexpr int KS = K + 4;        // padded stride (words); +16B keeps alignment
  constexpr int R = 8;
  __shared__ __align__(16) float Ws[COLT * KS];
  __shared__ __align__(16) float As[64 * KS];

  const int col0 = blockIdx.y * COLT;
  const int row0 = blockIdx.x * 64;
  const int tid = threadIdx.x;

  // Issue the whole A tile as cp.async 16B chunks.
  constexpr int CHUNKS = 64 * (K / 4);
#pragma unroll 4
  for (int c = tid; c < CHUNKS; c += 256) {
    int row = c / (K / 4), col4 = c % (K / 4);
    uint32_t saddr = (uint32_t)__cvta_generic_to_shared(&As[row * KS + col4 * 4]);
    cp_async16(saddr, A + (size_t)(row0 + row) * K + col4 * 4);
  }
  asm volatile("cp.async.commit_group;\n");

  // Stage W transposed while the A tile is in flight.
  for (int i = tid; i < COLT * K; i += 256) {
    int c = i / K, k = i - c * K;
    Ws[c * KS + k] = W[k * DOUT + col0 + c];
  }
  asm volatile("cp.async.wait_group 0;\n");
  __syncthreads();

  const int lane = tid & 31;
  const int warp = tid >> 5;

  ull acc[R][VPT];
#pragma unroll
  for (int r = 0; r < R; r++)
#pragma unroll
    for (int v = 0; v < VPT; v++) acc[r][v] = 0ull;

#pragma unroll 2
  for (int k = 0; k < K; k += 4) {
    ull w01[VPT], w23[VPT];
#pragma unroll
    for (int v = 0; v < VPT; v++) {
      float4 wv = *reinterpret_cast<const float4*>(&Ws[(lane + 32 * v) * KS + k]);
      w01[v] = reinterpret_cast<ull*>(&wv)[0];
      w23[v] = reinterpret_cast<ull*>(&wv)[1];
    }
#pragma unroll
    for (int r = 0; r < R; r++) {
      float4 av = *reinterpret_cast<const float4*>(&As[(warp * R + r) * KS + k]);
      ull a01 = reinterpret_cast<ull*>(&av)[0];
      ull a23 = reinterpret_cast<ull*>(&av)[1];
#pragma unroll
      for (int v = 0; v < VPT; v++) {
        acc[r][v] = ffma2(a01, w01[v], acc[r][v]);
        acc[r][v] = ffma2(a23, w23[v], acc[r][v]);
      }
    }
  }

#pragma unroll
  for (int r = 0; r < R; r++) {
#pragma unroll
    for (int v = 0; v < VPT; v++) {
      float s = hsum2(acc[r][v]);
      int c = col0 + lane + 32 * v;
      if (BIAS) s += __ldg(&bias[c]);
      if (RELU) s = fmaxf(s, 0.0f);
      out[(size_t)(row0 + warp * R + r) * DOUT + c] = s;
    }
  }
}

// ---------------- launch ------------------------------------------------------
extern "C" void kernel_launch(void* const* d_in, const int* in_sizes, int n_in,
                              void* d_out, int out_size) {
  (void)in_sizes; (void)n_in; (void)out_size;
  const float* x  = (const float*)d_in[0];
  const int*   ei = (const int*)d_in[1];
  const int* src = ei;
  const int* dst = ei + EE;
  const float* W1 = (const float*)d_in[3];
  const float* b1 = (const float*)d_in[4];
  const float* W2 = (const float*)d_in[5];
  const float* b2 = (const float*)d_in[6];
  const float* W3 = (const float*)d_in[7];
  const float* b3 = (const float*)d_in[8];
  const float* W4 = (const float*)d_in[9];
  const float* b4 = (const float*)d_in[10];
  const float* Wl = (const float*)d_in[11];
  const float* bl = (const float*)d_in[12];
  float* out = (float*)d_out;

  float *buf0, *buf1;
  cudaGetSymbolAddress((void**)&buf0, g_buf0);
  cudaGetSymbolAddress((void**)&buf1, g_buf1);

  static cudaStream_t s_prep = nullptr;
  static cudaEvent_t ev_fork = nullptr, ev_join = nullptr;
  if (s_prep == nullptr) {
    cudaStreamCreateWithFlags(&s_prep, cudaStreamNonBlocking);
    cudaEventCreateWithFlags(&ev_fork, cudaEventDisableTiming);
    cudaEventCreateWithFlags(&ev_join, cudaEventDisableTiming);
  }

  // ---- fork: CSR prep on s_prep, concurrent with gemm1 on the main stream.
  cudaEventRecord(ev_fork, 0);
  cudaStreamWaitEvent(s_prep, ev_fork, 0);

  count_deg_kernel<<<(EE + 255) / 256, 256, 0, s_prep>>>(dst);
  scan_fused_kernel<<<NSCAN_BLK, 256, 0, s_prep>>>();
  fill_csr_kernel<<<(NNZ + 255) / 256, 256, 0, s_prep>>>(src, dst);
  cudaEventRecord(ev_join, s_prep);

  const int GEMM_BLOCKS = NN / 64;    // 625
  const int AGG128_BLOCKS = NN / 8;   // 5000 (warp per node)
  const int AGG64_BLOCKS = NN / 16;   // 2500 (half-warp per node)

  // L1 GEMM overlaps prep: t = x @ W1
  gemm_kernel<128, 64, false, false><<<dim3(GEMM_BLOCKS, 1), 256>>>(x, W1, nullptr, buf0);

  cudaStreamWaitEvent(0, ev_join, 0);  // join: aggs need the CSR

  // h1 = relu(agg(t) + b1)
  agg64_kernel<true, true><<<AGG64_BLOCKS, 256>>>(buf0, b1, buf1);
  // L2 agg-first: a = agg(h1)
  agg64_kernel<false, false><<<AGG64_BLOCKS, 256>>>(buf1, nullptr, buf0);
  // h2 = relu(a @ W2 + b2)
  gemm_kernel<64, 128, true, true><<<dim3(GEMM_BLOCKS, 2), 256>>>(buf0, W2, b2, buf1);
  // t3 = h2 @ W3
  gemm_kernel<128, 128, false, false><<<dim3(GEMM_BLOCKS, 2), 256>>>(buf1, W3, nullptr, buf0);
  // h3 = relu(agg(t3) + b3)
  agg128_kernel<true, true><<<AGG128_BLOCKS, 256>>>(buf0, b3, buf1);
  // t4 = h3 @ W4
  gemm_kernel<128, 64, false, false><<<dim3(GEMM_BLOCKS, 1), 256>>>(buf1, W4, nullptr, buf0);
  // h4 = relu(agg(t4) + b4)
  agg64_kernel<true, true><<<AGG64_BLOCKS, 256>>>(buf0, b4, buf1);
  // Head: out = h4 @ Wl + bl
  gemm_kernel<64, 32, false, true><<<dim3(GEMM_BLOCKS, 1), 256>>>(buf1, Wl, bl, out);
}

// round 10
// speedup vs baseline: 1.4410x; 1.2804x over previous
#include <cuda_runtime.h>
#include <cstdint>

#define NN  40000
#define EE  640000
#define NNZ (EE + NN)   // 680000 (edges + self-loops)

#define NSCAN_BLK 40    // 40 blocks x 1000 elements = NN
#define SCAN_CH   1000

typedef unsigned long long ull;

// ---------------- scratch (device globals — no runtime allocation) ----------
__device__ __align__(256) float g_buf0[NN * 128];
__device__ __align__(256) float g_buf1[NN * 128];
__device__ float g_dinv[NN];
__device__ int   g_deg[NN];          // zero at load; scan re-zeroes after read
__device__ int   g_rowptr[NN + 1];
__device__ int   g_cursor[NN];
__device__ __align__(16) int2 g_adj[NNZ];   // {col, bitcast(weight)}
__device__ volatile int g_scan_flag[NSCAN_BLK];  // zero at load; consumer resets
__device__ volatile int g_scan_pref[NSCAN_BLK];

// ---------------- packed fp32x2 helpers (sm_10x) -----------------------------
__device__ __forceinline__ ull ffma2(ull a, ull b, ull c) {
  ull d;
  asm("fma.rn.f32x2 %0, %1, %2, %3;" : "=l"(d) : "l"(a), "l"(b), "l"(c));
  return d;
}
__device__ __forceinline__ float hsum2(ull v) {
  float lo, hi;
  asm("mov.b64 {%0, %1}, %2;" : "=f"(lo), "=f"(hi) : "l"(v));
  return lo + hi;
}
__device__ __forceinline__ ull pack2(float lo, float hi) {
  ull v;
  asm("mov.b64 %0, {%1, %2};" : "=l"(v) : "f"(lo), "f"(hi));
  return v;
}
__device__ __forceinline__ void cp_async16(uint32_t saddr, const void* gaddr) {
  asm volatile("cp.async.cg.shared.global [%0], [%1], 16;\n"
               :: "r"(saddr), "l"(gaddr));
}

// ---------------- preprocessing ---------------------------------------------
__global__ void count_deg_kernel(const int* __restrict__ dst) {
  int e = blockIdx.x * 256 + threadIdx.x;
  if (e < EE) atomicAdd(&g_deg[dst[e]], 1);
}

// One-kernel exclusive scan of (deg+1) via decoupled lookback. Also computes
// dinv and re-zeroes g_deg (restores the pre-run invariant for replays).
__global__ void __launch_bounds__(256) scan_fused_kernel() {
  __shared__ int warp_pref[8];
  __shared__ int s_base;
  const int b = blockIdx.x, t = threadIdx.x;
  const int lane = t & 31, warp = t >> 5;

  int v[4];
  int s = 0;
#pragma unroll
  for (int i = 0; i < 4; i++) {
    int li = t * 4 + i;
    int d1 = 0;
    if (li < SCAN_CH) {
      int idx = b * SCAN_CH + li;
      d1 = g_deg[idx] + 1;
      g_deg[idx] = 0;
      g_dinv[idx] = rsqrtf((float)d1);
    }
    v[i] = s;
    s += d1;
  }
  int ws = s;
#pragma unroll
  for (int off = 1; off < 32; off <<= 1) {
    int u = __shfl_up_sync(0xffffffffu, ws, off);
    if (lane >= off) ws += u;
  }
  if (lane == 31) warp_pref[warp] = ws;
  __syncthreads();
  if (t == 0) {
    int run = 0;
#pragma unroll
    for (int i = 0; i < 8; i++) { int x = warp_pref[i]; warp_pref[i] = run; run += x; }
    int pref = 0;
    if (b > 0) {
      while (g_scan_flag[b - 1] == 0) {}
      __threadfence();
      pref = g_scan_pref[b - 1];
      g_scan_flag[b - 1] = 0;
    }
    if (b < NSCAN_BLK - 1) {
      g_scan_pref[b] = pref + run;
      __threadfence();
      g_scan_flag[b] = 1;
    } else {
      g_rowptr[NN] = pref + run;
    }
    s_base = pref;
  }
  __syncthreads();
  const int base = s_base + warp_pref[warp] + (ws - s);
#pragma unroll
  for (int i = 0; i < 4; i++) {
    int li = t * 4 + i;
    if (li < SCAN_CH) {
      int idx = b * SCAN_CH + li;
      int p = base + v[i];
      g_rowptr[idx] = p;
      g_cursor[idx] = p;
    }
  }
}

__global__ void fill_csr_kernel(const int* __restrict__ src,
                                const int* __restrict__ dst) {
  int t = blockIdx.x * 256 + threadIdx.x;
  if (t < EE) {
    int s = src[t], d = dst[t];
    int pos = atomicAdd(&g_cursor[d], 1);
    g_adj[pos] = make_int2(s, __float_as_int(g_dinv[s] * g_dinv[d]));
  } else if (t < NNZ) {
    int i = t - EE;
    int pos = atomicAdd(&g_cursor[i], 1);
    float di = g_dinv[i];
    g_adj[pos] = make_int2(i, __float_as_int(di * di));
  }
}

// ---------------- shared row-aggregation primitive ---------------------------
#define AGG_ONE(cx, wy)                                                        \
  {                                                                            \
    float4 xx = __ldg(reinterpret_cast<const float4*>(Hin + (size_t)(cx) * D) + sub); \
    ull ww = pack2(__int_as_float(wy), __int_as_float(wy));                    \
    a01 = ffma2(reinterpret_cast<ull*>(&xx)[0], ww, a01);                      \
    a23 = ffma2(reinterpret_cast<ull*>(&xx)[1], ww, a23);                      \
  }

template <int D>
__device__ __forceinline__ float4 agg_row(const float* __restrict__ Hin,
                                          int node, int sub) {
  int e = g_rowptr[node];
  const int end = g_rowptr[node + 1];
  ull a01 = 0ull, a23 = 0ull;
  if ((e & 1) && e < end) {
    int2 av = __ldg(&g_adj[e]);
    AGG_ONE(av.x, av.y);
    e++;
  }
  for (; e + 8 <= end; e += 8) {
    int4 q0 = __ldg(reinterpret_cast<const int4*>(g_adj + e));
    int4 q1 = __ldg(reinterpret_cast<const int4*>(g_adj + e + 2));
    int4 q2 = __ldg(reinterpret_cast<const int4*>(g_adj + e + 4));
    int4 q3 = __ldg(reinterpret_cast<const int4*>(g_adj + e + 6));
    float4 x0 = __ldg(reinterpret_cast<const float4*>(Hin + (size_t)q0.x * D) + sub);
    float4 x1 = __ldg(reinterpret_cast<const float4*>(Hin + (size_t)q0.z * D) + sub);
    float4 x2 = __ldg(reinterpret_cast<const float4*>(Hin + (size_t)q1.x * D) + sub);
    float4 x3 = __ldg(reinterpret_cast<const float4*>(Hin + (size_t)q1.z * D) + sub);
    float4 x4 = __ldg(reinterpret_cast<const float4*>(Hin + (size_t)q2.x * D) + sub);
    float4 x5 = __ldg(reinterpret_cast<const float4*>(Hin + (size_t)q2.z * D) + sub);
    float4 x6 = __ldg(reinterpret_cast<const float4*>(Hin + (size_t)q3.x * D) + sub);
    float4 x7 = __ldg(reinterpret_cast<const float4*>(Hin + (size_t)q3.z * D) + sub);
    ull w0 = pack2(__int_as_float(q0.y), __int_as_float(q0.y));
    ull w1 = pack2(__int_as_float(q0.w), __int_as_float(q0.w));
    ull w2 = pack2(__int_as_float(q1.y), __int_as_float(q1.y));
    ull w3 = pack2(__int_as_float(q1.w), __int_as_float(q1.w));
    ull w4 = pack2(__int_as_float(q2.y), __int_as_float(q2.y));
    ull w5 = pack2(__int_as_float(q2.w), __int_as_float(q2.w));
    ull w6 = pack2(__int_as_float(q3.y), __int_as_float(q3.y));
    ull w7 = pack2(__int_as_float(q3.w), __int_as_float(q3.w));
    a01 = ffma2(reinterpret_cast<ull*>(&x0)[0], w0, a01);
    a23 = ffma2(reinterpret_cast<ull*>(&x0)[1], w0, a23);
    a01 = ffma2(reinterpret_cast<ull*>(&x1)[0], w1, a01);
    a23 = ffma2(reinterpret_cast<ull*>(&x1)[1], w1, a23);
    a01 = ffma2(reinterpret_cast<ull*>(&x2)[0], w2, a01);
    a23 = ffma2(reinterpret_cast<ull*>(&x2)[1], w2, a23);
    a01 = ffma2(reinterpret_cast<ull*>(&x3)[0], w3, a01);
    a23 = ffma2(reinterpret_cast<ull*>(&x3)[1], w3, a23);
    a01 = ffma2(reinterpret_cast<ull*>(&x4)[0], w4, a01);
    a23 = ffma2(reinterpret_cast<ull*>(&x4)[1], w4, a23);
    a01 = ffma2(reinterpret_cast<ull*>(&x5)[0], w5, a01);
    a23 = ffma2(reinterpret_cast<ull*>(&x5)[1], w5, a23);
    a01 = ffma2(reinterpret_cast<ull*>(&x6)[0], w6, a01);
    a23 = ffma2(reinterpret_cast<ull*>(&x6)[1], w6, a23);
    a01 = ffma2(reinterpret_cast<ull*>(&x7)[0], w7, a01);
    a23 = ffma2(reinterpret_cast<ull*>(&x7)[1], w7, a23);
  }
  for (; e + 2 <= end; e += 2) {
    int4 q = __ldg(reinterpret_cast<const int4*>(g_adj + e));
    AGG_ONE(q.x, q.y);
    AGG_ONE(q.z, q.w);
  }
  if (e < end) {
    int2 av = __ldg(&g_adj[e]);
    AGG_ONE(av.x, av.y);
  }
  float4 r;
  r.x = __int_as_float((int)(a01 & 0xffffffffull));
  r.y = __int_as_float((int)(a01 >> 32));
  r.z = __int_as_float((int)(a23 & 0xffffffffull));
  r.w = __int_as_float((int)(a23 >> 32));
  return r;
}
#undef AGG_ONE

__device__ __forceinline__ float4 bias_relu4(float4 a, const float* bias,
                                             int sub, bool do_bias, bool do_relu) {
  if (do_bias) {
    float4 b = __ldg(reinterpret_cast<const float4*>(bias) + sub);
    a.x += b.x; a.y += b.y; a.z += b.z; a.w += b.w;
  }
  if (do_relu) {
    a.x = fmaxf(a.x, 0.f); a.y = fmaxf(a.y, 0.f);
    a.z = fmaxf(a.z, 0.f); a.w = fmaxf(a.w, 0.f);
  }
  return a;
}

// ---------------- standalone aggregation kernels -----------------------------
template <bool RELU, bool BIAS>
__global__ void __launch_bounds__(256) agg64_kernel(
    const float* __restrict__ Hin, const float* __restrict__ bias,
    float* __restrict__ Hout) {
  const int node = blockIdx.x * 16 + (threadIdx.x >> 4);
  const int sub = threadIdx.x & 15;
  float4 acc = agg_row<64>(Hin, node, sub);
  acc = bias_relu4(acc, bias, sub, BIAS, RELU);
  reinterpret_cast<float4*>(Hout + (size_t)node * 64)[sub] = acc;
}

template <bool RELU, bool BIAS>
__global__ void __launch_bounds__(256) agg128_kernel(
    const float* __restrict__ Hin, const float* __restrict__ bias,
    float* __restrict__ Hout) {
  const int node = blockIdx.x * 8 + (threadIdx.x >> 5);
  const int sub = threadIdx.x & 31;
  float4 acc = agg_row<128>(Hin, node, sub);
  acc = bias_relu4(acc, bias, sub, BIAS, RELU);
  reinterpret_cast<float4*>(Hout + (size_t)node * 128)[sub] = acc;
}

// ---------------- dense: out[N,DOUT] = A[N,K] @ W[K,DOUT] (+bias)(relu) -----
// A tile (64 rows) staged via cp.async. W staged transposed with COALESCED
// global reads (consecutive threads -> consecutive columns of one W row;
// the transposed STS pays a ~4-way bank conflict, which is cheap smem-side).
template <int K, int DOUT, bool RELU, bool BIAS>
__global__ void __launch_bounds__(256) gemm_kernel(
    const float* __restrict__ A, const float* __restrict__ W,
    const float* __restrict__ bias, float* __restrict__ out) {
  constexpr int COLT = (DOUT < 64) ? DOUT : 64;
  constexpr int VPT = COLT / 32;   // 1 or 2
  constexpr int KS = K + 4;        // padded stride (words)
  constexpr int R = 8;
  __shared__ __align__(16) float Ws[COLT * KS];
  __shared__ __align__(16) float As[64 * KS];

  const int col0 = blockIdx.y * COLT;
  const int row0 = blockIdx.x * 64;
  const int tid = threadIdx.x;

  // Issue the whole A tile as cp.async 16B chunks.
  constexpr int CHUNKS = 64 * (K / 4);
#pragma unroll 4
  for (int c = tid; c < CHUNKS; c += 256) {
    int row = c / (K / 4), col4 = c % (K / 4);
    uint32_t saddr = (uint32_t)__cvta_generic_to_shared(&As[row * KS + col4 * 4]);
    cp_async16(saddr, A + (size_t)(row0 + row) * K + col4 * 4);
  }
  asm volatile("cp.async.commit_group;\n");

  // Stage W transposed; COALESCED reads (k outer, c inner).
  for (int i = tid; i < COLT * K; i += 256) {
    int k = i / COLT, c = i - k * COLT;
    Ws[c * KS + k] = __ldg(&W[k * DOUT + col0 + c]);
  }
  asm volatile("cp.async.wait_group 0;\n");
  __syncthreads();

  const int lane = tid & 31;
  const int warp = tid >> 5;

  ull acc[R][VPT];
#pragma unroll
  for (int r = 0; r < R; r++)
#pragma unroll
    for (int v = 0; v < VPT; v++) acc[r][v] = 0ull;

#pragma unroll 2
  for (int k = 0; k < K; k += 4) {
    ull w01[VPT], w23[VPT];
#pragma unroll
    for (int v = 0; v < VPT; v++) {
      float4 wv = *reinterpret_cast<const float4*>(&Ws[(lane + 32 * v) * KS + k]);
      w01[v] = reinterpret_cast<ull*>(&wv)[0];
      w23[v] = reinterpret_cast<ull*>(&wv)[1];
    }
#pragma unroll
    for (int r = 0; r < R; r++) {
      float4 av = *reinterpret_cast<const float4*>(&As[(warp * R + r) * KS + k]);
      ull a01 = reinterpret_cast<ull*>(&av)[0];
      ull a23 = reinterpret_cast<ull*>(&av)[1];
#pragma unroll
      for (int v = 0; v < VPT; v++) {
        acc[r][v] = ffma2(a01, w01[v], acc[r][v]);
        acc[r][v] = ffma2(a23, w23[v], acc[r][v]);
      }
    }
  }

#pragma unroll
  for (int r = 0; r < R; r++) {
#pragma unroll
    for (int v = 0; v < VPT; v++) {
      float s = hsum2(acc[r][v]);
      int c = col0 + lane + 32 * v;
      if (BIAS) s += __ldg(&bias[c]);
      if (RELU) s = fmaxf(s, 0.0f);
      out[(size_t)(row0 + warp * R + r) * DOUT + c] = s;
    }
  }
}

// ---------------- launch ------------------------------------------------------
extern "C" void kernel_launch(void* const* d_in, const int* in_sizes, int n_in,
                              void* d_out, int out_size) {
  (void)in_sizes; (void)n_in; (void)out_size;
  const float* x  = (const float*)d_in[0];
  const int*   ei = (const int*)d_in[1];
  const int* src = ei;
  const int* dst = ei + EE;
  const float* W1 = (const float*)d_in[3];
  const float* b1 = (const float*)d_in[4];
  const float* W2 = (const float*)d_in[5];
  const float* b2 = (const float*)d_in[6];
  const float* W3 = (const float*)d_in[7];
  const float* b3 = (const float*)d_in[8];
  const float* W4 = (const float*)d_in[9];
  const float* b4 = (const float*)d_in[10];
  const float* Wl = (const float*)d_in[11];
  const float* bl = (const float*)d_in[12];
  float* out = (float*)d_out;

  float *buf0, *buf1;
  cudaGetSymbolAddress((void**)&buf0, g_buf0);
  cudaGetSymbolAddress((void**)&buf1, g_buf1);

  static cudaStream_t s_prep = nullptr;
  static cudaEvent_t ev_fork = nullptr, ev_join = nullptr;
  if (s_prep == nullptr) {
    cudaStreamCreateWithFlags(&s_prep, cudaStreamNonBlocking);
    cudaEventCreateWithFlags(&ev_fork, cudaEventDisableTiming);
    cudaEventCreateWithFlags(&ev_join, cudaEventDisableTiming);
  }

  // ---- fork: CSR prep on s_prep, concurrent with gemm1 on the main stream.
  cudaEventRecord(ev_fork, 0);
  cudaStreamWaitEvent(s_prep, ev_fork, 0);

  count_deg_kernel<<<(EE + 255) / 256, 256, 0, s_prep>>>(dst);
  scan_fused_kernel<<<NSCAN_BLK, 256, 0, s_prep>>>();
  fill_csr_kernel<<<(NNZ + 255) / 256, 256, 0, s_prep>>>(src, dst);
  cudaEventRecord(ev_join, s_prep);

  const int GEMM_BLOCKS = NN / 64;    // 625
  const int AGG128_BLOCKS = NN / 8;   // 5000 (warp per node)
  const int AGG64_BLOCKS = NN / 16;   // 2500 (half-warp per node)

  // L1 GEMM overlaps prep: t = x @ W1
  gemm_kernel<128, 64, false, false><<<dim3(GEMM_BLOCKS, 1), 256>>>(x, W1, nullptr, buf0);

  cudaStreamWaitEvent(0, ev_join, 0);  // join: aggs need the CSR

  // h1 = relu(agg(t) + b1)
  agg64_kernel<true, true><<<AGG64_BLOCKS, 256>>>(buf0, b1, buf1);
  // L2 agg-first: a = agg(h1)
  agg64_kernel<false, false><<<AGG64_BLOCKS, 256>>>(buf1, nullptr, buf0);
  // h2 = relu(a @ W2 + b2)
  gemm_kernel<64, 128, true, true><<<dim3(GEMM_BLOCKS, 2), 256>>>(buf0, W2, b2, buf1);
  // t3 = h2 @ W3
  gemm_kernel<128, 128, false, false><<<dim3(GEMM_BLOCKS, 2), 256>>>(buf1, W3, nullptr, buf0);
  // h3 = relu(agg(t3) + b3)
  agg128_kernel<true, true><<<AGG128_BLOCKS, 256>>>(buf0, b3, buf1);
  // t4 = h3 @ W4
  gemm_kernel<128, 64, false, false><<<dim3(GEMM_BLOCKS, 1), 256>>>(buf1, W4, nullptr, buf0);
  // h4 = relu(agg(t4) + b4)
  agg64_kernel<true, true><<<AGG64_BLOCKS, 256>>>(buf0, b4, buf1);
  // Head: out = h4 @ Wl + bl
  gemm_kernel<64, 32, false, true><<<dim3(GEMM_BLOCKS, 1), 256>>>(buf1, Wl, bl, out);
}

// round 11
// speedup vs baseline: 1.5035x; 1.0434x over previous
#include <cuda_runtime.h>
#include <cuda_fp16.h>
#include <cstdint>

#define NN  40000
#define EE  640000
#define NNZ (EE + NN)   // 680000 (edges + self-loops)

#define NSCAN_BLK 40
#define SCAN_CH   1000

typedef unsigned long long ull;

// ---------------- scratch (device globals — no runtime allocation) ----------
__device__ __align__(256) float  g_buf0[NN * 128];
__device__ __align__(256) float  g_buf1[NN * 128];
__device__ __align__(256) __half g_hbuf0[NN * 128];
__device__ __align__(256) __half g_hbuf1[NN * 128];
__device__ float g_dinv[NN];
__device__ int   g_deg[NN];          // zero at load; scan re-zeroes after read
__device__ int   g_rowptr[NN + 1];
__device__ int   g_cursor[NN];
__device__ __align__(16) int2 g_adj[NNZ];   // {col, bitcast(weight)}
__device__ volatile int g_scan_flag[NSCAN_BLK];
__device__ volatile int g_scan_pref[NSCAN_BLK];

// ---------------- packed fp32x2 helpers (sm_10x) -----------------------------
__device__ __forceinline__ ull ffma2(ull a, ull b, ull c) {
  ull d;
  asm("fma.rn.f32x2 %0, %1, %2, %3;" : "=l"(d) : "l"(a), "l"(b), "l"(c));
  return d;
}
__device__ __forceinline__ float hsum2(ull v) {
  float lo, hi;
  asm("mov.b64 {%0, %1}, %2;" : "=f"(lo), "=f"(hi) : "l"(v));
  return lo + hi;
}
__device__ __forceinline__ ull pack2(float lo, float hi) {
  ull v;
  asm("mov.b64 %0, {%1, %2};" : "=l"(v) : "f"(lo), "f"(hi));
  return v;
}
__device__ __forceinline__ ull h2ull(uint32_t h) {  // half2 -> packed float2
  __half2 hh = *reinterpret_cast<__half2*>(&h);
  float2 f = __half22float2(hh);
  return *reinterpret_cast<ull*>(&f);
}
__device__ __forceinline__ float2 u2f2(ull v) {
  return *reinterpret_cast<float2*>(&v);
}
__device__ __forceinline__ void cp_async16(uint32_t saddr, const void* gaddr) {
  asm volatile("cp.async.cg.shared.global [%0], [%1], 16;\n"
               :: "r"(saddr), "l"(gaddr));
}

// ---------------- preprocessing ---------------------------------------------
__global__ void count_deg_kernel(const int* __restrict__ dst) {
  int e = blockIdx.x * 256 + threadIdx.x;
  if (e < EE) atomicAdd(&g_deg[dst[e]], 1);
}

__global__ void __launch_bounds__(256) scan_fused_kernel() {
  __shared__ int warp_pref[8];
  __shared__ int s_base;
  const int b = blockIdx.x, t = threadIdx.x;
  const int lane = t & 31, warp = t >> 5;

  int v[4];
  int s = 0;
#pragma unroll
  for (int i = 0; i < 4; i++) {
    int li = t * 4 + i;
    int d1 = 0;
    if (li < SCAN_CH) {
      int idx = b * SCAN_CH + li;
      d1 = g_deg[idx] + 1;
      g_deg[idx] = 0;
      g_dinv[idx] = rsqrtf((float)d1);
    }
    v[i] = s;
    s += d1;
  }
  int ws = s;
#pragma unroll
  for (int off = 1; off < 32; off <<= 1) {
    int u = __shfl_up_sync(0xffffffffu, ws, off);
    if (lane >= off) ws += u;
  }
  if (lane == 31) warp_pref[warp] = ws;
  __syncthreads();
  if (t == 0) {
    int run = 0;
#pragma unroll
    for (int i = 0; i < 8; i++) { int x = warp_pref[i]; warp_pref[i] = run; run += x; }
    int pref = 0;
    if (b > 0) {
      while (g_scan_flag[b - 1] == 0) {}
      __threadfence();
      pref = g_scan_pref[b - 1];
      g_scan_flag[b - 1] = 0;
    }
    if (b < NSCAN_BLK - 1) {
      g_scan_pref[b] = pref + run;
      __threadfence();
      g_scan_flag[b] = 1;
    } else {
      g_rowptr[NN] = pref + run;
    }
    s_base = pref;
  }
  __syncthreads();
  const int base = s_base + warp_pref[warp] + (ws - s);
#pragma unroll
  for (int i = 0; i < 4; i++) {
    int li = t * 4 + i;
    if (li < SCAN_CH) {
      int idx = b * SCAN_CH + li;
      int p = base + v[i];
      g_rowptr[idx] = p;
      g_cursor[idx] = p;
    }
  }
}

__global__ void fill_csr_kernel(const int* __restrict__ src,
                                const int* __restrict__ dst) {
  int t = blockIdx.x * 256 + threadIdx.x;
  if (t < EE) {
    int s = src[t], d = dst[t];
    int pos = atomicAdd(&g_cursor[d], 1);
    g_adj[pos] = make_int2(s, __float_as_int(g_dinv[s] * g_dinv[d]));
  } else if (t < NNZ) {
    int i = t - EE;
    int pos = atomicAdd(&g_cursor[i], 1);
    float di = g_dinv[i];
    g_adj[pos] = make_int2(i, __float_as_int(di * di));
  }
}

// ---------------- fp16-input aggregation -------------------------------------
// Hin rows are D fp16 = D*2 bytes; LANES = D/8 threads per node, each thread
// covering 8 features via one 16B gather. Accumulate fp32 (fma.f32x2).
#define AGGH_ONE(cx, wy)                                                       \
  {                                                                            \
    uint4 xx = __ldg(reinterpret_cast<const uint4*>(Hin + (size_t)(cx) * D) + sub); \
    ull ww = pack2(__int_as_float(wy), __int_as_float(wy));                    \
    a0 = ffma2(h2ull(xx.x), ww, a0);                                           \
    a1 = ffma2(h2ull(xx.y), ww, a1);                                           \
    a2 = ffma2(h2ull(xx.z), ww, a2);                                           \
    a3 = ffma2(h2ull(xx.w), ww, a3);                                           \
  }

template <int D, bool RELU, bool BIAS, bool OUTH>
__global__ void __launch_bounds__(256) aggh_kernel(
    const __half* __restrict__ Hin, const float* __restrict__ bias,
    void* __restrict__ Hout) {
  constexpr int LANES = D / 8;
  const int node = blockIdx.x * (256 / LANES) + threadIdx.x / LANES;
  const int sub = threadIdx.x % LANES;
  int e = g_rowptr[node];
  const int end = g_rowptr[node + 1];

  ull a0 = 0ull, a1 = 0ull, a2 = 0ull, a3 = 0ull;
  if ((e & 1) && e < end) {
    int2 av = __ldg(&g_adj[e]);
    AGGH_ONE(av.x, av.y);
    e++;
  }
  for (; e + 4 <= end; e += 4) {
    int4 q0 = __ldg(reinterpret_cast<const int4*>(g_adj + e));
    int4 q1 = __ldg(reinterpret_cast<const int4*>(g_adj + e + 2));
    uint4 x0 = __ldg(reinterpret_cast<const uint4*>(Hin + (size_t)q0.x * D) + sub);
    uint4 x1 = __ldg(reinterpret_cast<const uint4*>(Hin + (size_t)q0.z * D) + sub);
    uint4 x2 = __ldg(reinterpret_cast<const uint4*>(Hin + (size_t)q1.x * D) + sub);
    uint4 x3 = __ldg(reinterpret_cast<const uint4*>(Hin + (size_t)q1.z * D) + sub);
    ull w0 = pack2(__int_as_float(q0.y), __int_as_float(q0.y));
    ull w1 = pack2(__int_as_float(q0.w), __int_as_float(q0.w));
    ull w2 = pack2(__int_as_float(q1.y), __int_as_float(q1.y));
    ull w3 = pack2(__int_as_float(q1.w), __int_as_float(q1.w));
    a0 = ffma2(h2ull(x0.x), w0, a0);
    a1 = ffma2(h2ull(x0.y), w0, a1);
    a2 = ffma2(h2ull(x0.z), w0, a2);
    a3 = ffma2(h2ull(x0.w), w0, a3);
    a0 = ffma2(h2ull(x1.x), w1, a0);
    a1 = ffma2(h2ull(x1.y), w1, a1);
    a2 = ffma2(h2ull(x1.z), w1, a2);
    a3 = ffma2(h2ull(x1.w), w1, a3);
    a0 = ffma2(h2ull(x2.x), w2, a0);
    a1 = ffma2(h2ull(x2.y), w2, a1);
    a2 = ffma2(h2ull(x2.z), w2, a2);
    a3 = ffma2(h2ull(x2.w), w2, a3);
    a0 = ffma2(h2ull(x3.x), w3, a0);
    a1 = ffma2(h2ull(x3.y), w3, a1);
    a2 = ffma2(h2ull(x3.z), w3, a2);
    a3 = ffma2(h2ull(x3.w), w3, a3);
  }
  for (; e + 2 <= end; e += 2) {
    int4 q = __ldg(reinterpret_cast<const int4*>(g_adj + e));
    AGGH_ONE(q.x, q.y);
    AGGH_ONE(q.z, q.w);
  }
  if (e < end) {
    int2 av = __ldg(&g_adj[e]);
    AGGH_ONE(av.x, av.y);
  }

  float2 r0 = u2f2(a0), r1 = u2f2(a1), r2 = u2f2(a2), r3 = u2f2(a3);
  if (BIAS) {
    float4 b0 = __ldg(reinterpret_cast<const float4*>(bias) + sub * 2);
    float4 b1 = __ldg(reinterpret_cast<const float4*>(bias) + sub * 2 + 1);
    r0.x += b0.x; r0.y += b0.y; r1.x += b0.z; r1.y += b0.w;
    r2.x += b1.x; r2.y += b1.y; r3.x += b1.z; r3.y += b1.w;
  }
  if (RELU) {
    r0.x = fmaxf(r0.x, 0.f); r0.y = fmaxf(r0.y, 0.f);
    r1.x = fmaxf(r1.x, 0.f); r1.y = fmaxf(r1.y, 0.f);
    r2.x = fmaxf(r2.x, 0.f); r2.y = fmaxf(r2.y, 0.f);
    r3.x = fmaxf(r3.x, 0.f); r3.y = fmaxf(r3.y, 0.f);
  }
  if (OUTH) {
    uint4 o;
    __half2 h0 = __floats2half2_rn(r0.x, r0.y);
    __half2 h1 = __floats2half2_rn(r1.x, r1.y);
    __half2 h2 = __floats2half2_rn(r2.x, r2.y);
    __half2 h3 = __floats2half2_rn(r3.x, r3.y);
    o.x = *reinterpret_cast<uint32_t*>(&h0);
    o.y = *reinterpret_cast<uint32_t*>(&h1);
    o.z = *reinterpret_cast<uint32_t*>(&h2);
    o.w = *reinterpret_cast<uint32_t*>(&h3);
    reinterpret_cast<uint4*>((__half*)Hout + (size_t)node * D)[sub] = o;
  } else {
    float4* orow = reinterpret_cast<float4*>((float*)Hout + (size_t)node * D);
    orow[sub * 2] = make_float4(r0.x, r0.y, r1.x, r1.y);
    orow[sub * 2 + 1] = make_float4(r2.x, r2.y, r3.x, r3.y);
  }
}
#undef AGGH_ONE

// ---------------- dense: out[N,DOUT] = A[N,K] @ W[K,DOUT] (+bias)(relu) -----
// A (fp32) staged via cp.async; W staged transposed with coalesced reads.
// OUTH: write fp16 output (consumer is an aggregation).
template <int K, int DOUT, bool RELU, bool BIAS, bool OUTH>
__global__ void __launch_bounds__(256) gemm_kernel(
    const float* __restrict__ A, const float* __restrict__ W,
    const float* __restrict__ bias, void* __restrict__ out) {
  constexpr int COLT = (DOUT < 64) ? DOUT : 64;
  constexpr int VPT = COLT / 32;   // 1 or 2
  constexpr int KS = K + 4;
  constexpr int R = 8;
  __shared__ __align__(16) float Ws[COLT * KS];
  __shared__ __align__(16) float As[64 * KS];

  const int col0 = blockIdx.y * COLT;
  const int row0 = blockIdx.x * 64;
  const int tid = threadIdx.x;

  constexpr int CHUNKS = 64 * (K / 4);
#pragma unroll 4
  for (int c = tid; c < CHUNKS; c += 256) {
    int row = c / (K / 4), col4 = c % (K / 4);
    uint32_t saddr = (uint32_t)__cvta_generic_to_shared(&As[row * KS + col4 * 4]);
    cp_async16(saddr, A + (size_t)(row0 + row) * K + col4 * 4);
  }
  asm volatile("cp.async.commit_group;\n");

  for (int i = tid; i < COLT * K; i += 256) {
    int k = i / COLT, c = i - k * COLT;
    Ws[c * KS + k] = __ldg(&W[k * DOUT + col0 + c]);
  }
  asm volatile("cp.async.wait_group 0;\n");
  __syncthreads();

  const int lane = tid & 31;
  const int warp = tid >> 5;

  ull acc[R][VPT];
#pragma unroll
  for (int r = 0; r < R; r++)
#pragma unroll
    for (int v = 0; v < VPT; v++) acc[r][v] = 0ull;

#pragma unroll 2
  for (int k = 0; k < K; k += 4) {
    ull w01[VPT], w23[VPT];
#pragma unroll
    for (int v = 0; v < VPT; v++) {
      float4 wv = *reinterpret_cast<const float4*>(&Ws[(lane + 32 * v) * KS + k]);
      w01[v] = reinterpret_cast<ull*>(&wv)[0];
      w23[v] = reinterpret_cast<ull*>(&wv)[1];
    }
#pragma unroll
    for (int r = 0; r < R; r++) {
      float4 av = *reinterpret_cast<const float4*>(&As[(warp * R + r) * KS + k]);
      ull a01 = reinterpret_cast<ull*>(&av)[0];
      ull a23 = reinterpret_cast<ull*>(&av)[1];
#pragma unroll
      for (int v = 0; v < VPT; v++) {
        acc[r][v] = ffma2(a01, w01[v], acc[r][v]);
        acc[r][v] = ffma2(a23, w23[v], acc[r][v]);
      }
    }
  }

#pragma unroll
  for (int r = 0; r < R; r++) {
#pragma unroll
    for (int v = 0; v < VPT; v++) {
      float s = hsum2(acc[r][v]);
      int c = col0 + lane + 32 * v;
      if (BIAS) s += __ldg(&bias[c]);
      if (RELU) s = fmaxf(s, 0.0f);
      if (OUTH)
        ((__half*)out)[(size_t)(row0 + warp * R + r) * DOUT + c] = __float2half_rn(s);
      else
        ((float*)out)[(size_t)(row0 + warp * R + r) * DOUT + c] = s;
    }
  }
}

// ---------------- launch ------------------------------------------------------
extern "C" void kernel_launch(void* const* d_in, const int* in_sizes, int n_in,
                              void* d_out, int out_size) {
  (void)in_sizes; (void)n_in; (void)out_size;
  const float* x  = (const float*)d_in[0];
  const int*   ei = (const int*)d_in[1];
  const int* src = ei;
  const int* dst = ei + EE;
  const float* W1 = (const float*)d_in[3];
  const float* b1 = (const float*)d_in[4];
  const float* W2 = (const float*)d_in[5];
  const float* b2 = (const float*)d_in[6];
  const float* W3 = (const float*)d_in[7];
  const float* b3 = (const float*)d_in[8];
  const float* W4 = (const float*)d_in[9];
  const float* b4 = (const float*)d_in[10];
  const float* Wl = (const float*)d_in[11];
  const float* bl = (const float*)d_in[12];
  float* out = (float*)d_out;

  float *buf0, *buf1;
  __half *hbuf0, *hbuf1;
  cudaGetSymbolAddress((void**)&buf0, g_buf0);
  cudaGetSymbolAddress((void**)&buf1, g_buf1);
  cudaGetSymbolAddress((void**)&hbuf0, g_hbuf0);
  cudaGetSymbolAddress((void**)&hbuf1, g_hbuf1);

  static cudaStream_t s_prep = nullptr;
  static cudaEvent_t ev_fork = nullptr, ev_join = nullptr;
  if (s_prep == nullptr) {
    cudaStreamCreateWithFlags(&s_prep, cudaStreamNonBlocking);
    cudaEventCreateWithFlags(&ev_fork, cudaEventDisableTiming);
    cudaEventCreateWithFlags(&ev_join, cudaEventDisableTiming);
  }

  // ---- fork: CSR prep on s_prep, concurrent with gemm1 on the main stream.
  cudaEventRecord(ev_fork, 0);
  cudaStreamWaitEvent(s_prep, ev_fork, 0);

  count_deg_kernel<<<(EE + 255) / 256, 256, 0, s_prep>>>(dst);
  scan_fused_kernel<<<NSCAN_BLK, 256, 0, s_prep>>>();
  fill_csr_kernel<<<(NNZ + 255) / 256, 256, 0, s_prep>>>(src, dst);
  cudaEventRecord(ev_join, s_prep);

  const int GEMM_BLOCKS = NN / 64;      // 625
  const int AGGH64_BLOCKS = NN / 32;    // 1250 (8 lanes/node)
  const int AGGH128_BLOCKS = NN / 16;   // 2500 (16 lanes/node)

  // L1 GEMM overlaps prep: t = x @ W1 -> fp16
  gemm_kernel<128, 64, false, false, true>
      <<<dim3(GEMM_BLOCKS, 1), 256>>>(x, W1, nullptr, hbuf0);

  cudaStreamWaitEvent(0, ev_join, 0);  // join: aggs need the CSR

  // h1 = relu(agg(t) + b1) -> fp16 (it feeds another aggregation)
  aggh_kernel<64, true, true, true><<<AGGH64_BLOCKS, 256>>>(hbuf0, b1, hbuf1);
  // a = agg(h1) -> fp32 (feeds gemm)
  aggh_kernel<64, false, false, false><<<AGGH64_BLOCKS, 256>>>(hbuf1, nullptr, buf0);
  // h2 = relu(a @ W2 + b2) -> fp32 (feeds gemm)
  gemm_kernel<64, 128, true, true, false>
      <<<dim3(GEMM_BLOCKS, 2), 256>>>(buf0, W2, b2, buf1);
  // t3 = h2 @ W3 -> fp16 (feeds agg)
  gemm_kernel<128, 128, false, false, true>
      <<<dim3(GEMM_BLOCKS, 2), 256>>>(buf1, W3, nullptr, hbuf0);
  // h3 = relu(agg(t3) + b3) -> fp32
  aggh_kernel<128, true, true, false><<<AGGH128_BLOCKS, 256>>>(hbuf0, b3, buf0);
  // t4 = h3 @ W4 -> fp16 (feeds agg)
  gemm_kernel<128, 64, false, false, true>
      <<<dim3(GEMM_BLOCKS, 1), 256>>>(buf0, W4, nullptr, hbuf1);
  // h4 = relu(agg(t4) + b4) -> fp32
  aggh_kernel<64, true, true, false><<<AGGH64_BLOCKS, 256>>>(hbuf1, b4, buf1);
  // Head: out = h4 @ Wl + bl -> fp32
  gemm_kernel<64, 32, false, true, false>
      <<<dim3(GEMM_BLOCKS, 1), 256>>>(buf1, Wl, bl, out);
}

// round 12
// speedup vs baseline: 1.9459x; 1.2942x over previous
#include <cuda_runtime.h>
#include <cuda_fp16.h>
#include <cstdint>

#define NN  40000
#define EE  640000
#define NNZ (EE + NN)   // 680000 (edges + self-loops)

#define NSCAN_BLK 40
#define SCAN_CH   1000

typedef unsigned long long ull;

// ---------------- scratch (device globals — no runtime allocation) ----------
__device__ __align__(256) float  g_buf0[NN * 128];
__device__ __align__(256) __half g_hbuf0[NN * 128];
__device__ __align__(256) __half g_hbuf1[NN * 128];
__device__ float g_dinv[NN];
__device__ int   g_deg[NN];          // zero at load; scan re-zeroes after read
__device__ int   g_rowptr[NN + 1];
__device__ int   g_cursor[NN];
__device__ __align__(16) int2 g_adj[NNZ];   // {col, bitcast(weight)}
__device__ volatile int g_scan_flag[NSCAN_BLK];
__device__ volatile int g_scan_pref[NSCAN_BLK];

// ---------------- helpers -----------------------------------------------------
__device__ __forceinline__ ull ffma2(ull a, ull b, ull c) {
  ull d;
  asm("fma.rn.f32x2 %0, %1, %2, %3;" : "=l"(d) : "l"(a), "l"(b), "l"(c));
  return d;
}
__device__ __forceinline__ float hsum2(ull v) {
  float lo, hi;
  asm("mov.b64 {%0, %1}, %2;" : "=f"(lo), "=f"(hi) : "l"(v));
  return lo + hi;
}
__device__ __forceinline__ ull pack2(float lo, float hi) {
  ull v;
  asm("mov.b64 %0, {%1, %2};" : "=l"(v) : "f"(lo), "f"(hi));
  return v;
}
__device__ __forceinline__ ull h2ull(uint32_t h) {  // half2 -> packed float2
  __half2 hh = *reinterpret_cast<__half2*>(&h);
  float2 f = __half22float2(hh);
  return *reinterpret_cast<ull*>(&f);
}
__device__ __forceinline__ float2 u2f2(ull v) {
  return *reinterpret_cast<float2*>(&v);
}
__device__ __forceinline__ void cp_async16(uint32_t saddr, const void* gaddr) {
  asm volatile("cp.async.cg.shared.global [%0], [%1], 16;\n"
               :: "r"(saddr), "l"(gaddr));
}
__device__ __forceinline__ uint32_t s2u(const void* p) {
  return (uint32_t)__cvta_generic_to_shared(p);
}
__device__ __forceinline__ void ldsm_x4(uint32_t& r0, uint32_t& r1,
                                        uint32_t& r2, uint32_t& r3, uint32_t a) {
  asm volatile("ldmatrix.sync.aligned.m8n8.x4.shared.b16 {%0,%1,%2,%3}, [%4];"
               : "=r"(r0), "=r"(r1), "=r"(r2), "=r"(r3) : "r"(a));
}
__device__ __forceinline__ void ldsm_x4_t(uint32_t& r0, uint32_t& r1,
                                          uint32_t& r2, uint32_t& r3, uint32_t a) {
  asm volatile("ldmatrix.sync.aligned.m8n8.x4.trans.shared.b16 {%0,%1,%2,%3}, [%4];"
               : "=r"(r0), "=r"(r1), "=r"(r2), "=r"(r3) : "r"(a));
}
__device__ __forceinline__ void mma16816(float* c, uint32_t a0, uint32_t a1,
                                         uint32_t a2, uint32_t a3,
                                         uint32_t b0, uint32_t b1) {
  asm volatile(
      "mma.sync.aligned.m16n8k16.row.col.f32.f16.f16.f32 "
      "{%0,%1,%2,%3}, {%4,%5,%6,%7}, {%8,%9}, {%0,%1,%2,%3};"
      : "+f"(c[0]), "+f"(c[1]), "+f"(c[2]), "+f"(c[3])
      : "r"(a0), "r"(a1), "r"(a2), "r"(a3), "r"(b0), "r"(b1));
}

// ---------------- preprocessing ---------------------------------------------
__global__ void count_deg_kernel(const int* __restrict__ dst) {
  int e = blockIdx.x * 256 + threadIdx.x;
  if (e < EE) atomicAdd(&g_deg[dst[e]], 1);
}

__global__ void __launch_bounds__(256) scan_fused_kernel() {
  __shared__ int warp_pref[8];
  __shared__ int s_base;
  const int b = blockIdx.x, t = threadIdx.x;
  const int lane = t & 31, warp = t >> 5;

  int v[4];
  int s = 0;
#pragma unroll
  for (int i = 0; i < 4; i++) {
    int li = t * 4 + i;
    int d1 = 0;
    if (li < SCAN_CH) {
      int idx = b * SCAN_CH + li;
      d1 = g_deg[idx] + 1;
      g_deg[idx] = 0;
      g_dinv[idx] = rsqrtf((float)d1);
    }
    v[i] = s;
    s += d1;
  }
  int ws = s;
#pragma unroll
  for (int off = 1; off < 32; off <<= 1) {
    int u = __shfl_up_sync(0xffffffffu, ws, off);
    if (lane >= off) ws += u;
  }
  if (lane == 31) warp_pref[warp] = ws;
  __syncthreads();
  if (t == 0) {
    int run = 0;
#pragma unroll
    for (int i = 0; i < 8; i++) { int x = warp_pref[i]; warp_pref[i] = run; run += x; }
    int pref = 0;
    if (b > 0) {
      while (g_scan_flag[b - 1] == 0) {}
      __threadfence();
      pref = g_scan_pref[b - 1];
      g_scan_flag[b - 1] = 0;
    }
    if (b < NSCAN_BLK - 1) {
      g_scan_pref[b] = pref + run;
      __threadfence();
      g_scan_flag[b] = 1;
    } else {
      g_rowptr[NN] = pref + run;
    }
    s_base = pref;
  }
  __syncthreads();
  const int base = s_base + warp_pref[warp] + (ws - s);
#pragma unroll
  for (int i = 0; i < 4; i++) {
    int li = t * 4 + i;
    if (li < SCAN_CH) {
      int idx = b * SCAN_CH + li;
      int p = base + v[i];
      g_rowptr[idx] = p;
      g_cursor[idx] = p;
    }
  }
}

__global__ void fill_csr_kernel(const int* __restrict__ src,
                                const int* __restrict__ dst) {
  int t = blockIdx.x * 256 + threadIdx.x;
  if (t < EE) {
    int s = src[t], d = dst[t];
    int pos = atomicAdd(&g_cursor[d], 1);
    g_adj[pos] = make_int2(s, __float_as_int(g_dinv[s] * g_dinv[d]));
  } else if (t < NNZ) {
    int i = t - EE;
    int pos = atomicAdd(&g_cursor[i], 1);
    float di = g_dinv[i];
    g_adj[pos] = make_int2(i, __float_as_int(di * di));
  }
}

// ---------------- fp16-input aggregation -------------------------------------
#define AGGH_ONE(cx, wy)                                                       \
  {                                                                            \
    uint4 xx = __ldg(reinterpret_cast<const uint4*>(Hin + (size_t)(cx) * D) + sub); \
    ull ww = pack2(__int_as_float(wy), __int_as_float(wy));                    \
    a0 = ffma2(h2ull(xx.x), ww, a0);                                           \
    a1 = ffma2(h2ull(xx.y), ww, a1);                                           \
    a2 = ffma2(h2ull(xx.z), ww, a2);                                           \
    a3 = ffma2(h2ull(xx.w), ww, a3);                                           \
  }

template <int D, bool RELU, bool BIAS, bool OUTH>
__global__ void __launch_bounds__(256) aggh_kernel(
    const __half* __restrict__ Hin, const float* __restrict__ bias,
    void* __restrict__ Hout) {
  constexpr int LANES = D / 8;
  const int node = blockIdx.x * (256 / LANES) + threadIdx.x / LANES;
  const int sub = threadIdx.x % LANES;
  int e = g_rowptr[node];
  const int end = g_rowptr[node + 1];

  ull a0 = 0ull, a1 = 0ull, a2 = 0ull, a3 = 0ull;
  if ((e & 1) && e < end) {
    int2 av = __ldg(&g_adj[e]);
    AGGH_ONE(av.x, av.y);
    e++;
  }
  for (; e + 4 <= end; e += 4) {
    int4 q0 = __ldg(reinterpret_cast<const int4*>(g_adj + e));
    int4 q1 = __ldg(reinterpret_cast<const int4*>(g_adj + e + 2));
    uint4 x0 = __ldg(reinterpret_cast<const uint4*>(Hin + (size_t)q0.x * D) + sub);
    uint4 x1 = __ldg(reinterpret_cast<const uint4*>(Hin + (size_t)q0.z * D) + sub);
    uint4 x2 = __ldg(reinterpret_cast<const uint4*>(Hin + (size_t)q1.x * D) + sub);
    uint4 x3 = __ldg(reinterpret_cast<const uint4*>(Hin + (size_t)q1.z * D) + sub);
    ull w0 = pack2(__int_as_float(q0.y), __int_as_float(q0.y));
    ull w1 = pack2(__int_as_float(q0.w), __int_as_float(q0.w));
    ull w2 = pack2(__int_as_float(q1.y), __int_as_float(q1.y));
    ull w3 = pack2(__int_as_float(q1.w), __int_as_float(q1.w));
    a0 = ffma2(h2ull(x0.x), w0, a0);
    a1 = ffma2(h2ull(x0.y), w0, a1);
    a2 = ffma2(h2ull(x0.z), w0, a2);
    a3 = ffma2(h2ull(x0.w), w0, a3);
    a0 = ffma2(h2ull(x1.x), w1, a0);
    a1 = ffma2(h2ull(x1.y), w1, a1);
    a2 = ffma2(h2ull(x1.z), w1, a2);
    a3 = ffma2(h2ull(x1.w), w1, a3);
    a0 = ffma2(h2ull(x2.x), w2, a0);
    a1 = ffma2(h2ull(x2.y), w2, a1);
    a2 = ffma2(h2ull(x2.z), w2, a2);
    a3 = ffma2(h2ull(x2.w), w2, a3);
    a0 = ffma2(h2ull(x3.x), w3, a0);
    a1 = ffma2(h2ull(x3.y), w3, a1);
    a2 = ffma2(h2ull(x3.z), w3, a2);
    a3 = ffma2(h2ull(x3.w), w3, a3);
  }
  for (; e + 2 <= end; e += 2) {
    int4 q = __ldg(reinterpret_cast<const int4*>(g_adj + e));
    AGGH_ONE(q.x, q.y);
    AGGH_ONE(q.z, q.w);
  }
  if (e < end) {
    int2 av = __ldg(&g_adj[e]);
    AGGH_ONE(av.x, av.y);
  }

  float2 r0 = u2f2(a0), r1 = u2f2(a1), r2 = u2f2(a2), r3 = u2f2(a3);
  if (BIAS) {
    float4 b0 = __ldg(reinterpret_cast<const float4*>(bias) + sub * 2);
    float4 b1 = __ldg(reinterpret_cast<const float4*>(bias) + sub * 2 + 1);
    r0.x += b0.x; r0.y += b0.y; r1.x += b0.z; r1.y += b0.w;
    r2.x += b1.x; r2.y += b1.y; r3.x += b1.z; r3.y += b1.w;
  }
  if (RELU) {
    r0.x = fmaxf(r0.x, 0.f); r0.y = fmaxf(r0.y, 0.f);
    r1.x = fmaxf(r1.x, 0.f); r1.y = fmaxf(r1.y, 0.f);
    r2.x = fmaxf(r2.x, 0.f); r2.y = fmaxf(r2.y, 0.f);
    r3.x = fmaxf(r3.x, 0.f); r3.y = fmaxf(r3.y, 0.f);
  }
  if (OUTH) {
    uint4 o;
    __half2 h0 = __floats2half2_rn(r0.x, r0.y);
    __half2 h1 = __floats2half2_rn(r1.x, r1.y);
    __half2 h2 = __floats2half2_rn(r2.x, r2.y);
    __half2 h3 = __floats2half2_rn(r3.x, r3.y);
    o.x = *reinterpret_cast<uint32_t*>(&h0);
    o.y = *reinterpret_cast<uint32_t*>(&h1);
    o.z = *reinterpret_cast<uint32_t*>(&h2);
    o.w = *reinterpret_cast<uint32_t*>(&h3);
    reinterpret_cast<uint4*>((__half*)Hout + (size_t)node * D)[sub] = o;
  } else {
    float4* orow = reinterpret_cast<float4*>((float*)Hout + (size_t)node * D);
    orow[sub * 2] = make_float4(r0.x, r0.y, r1.x, r1.y);
    orow[sub * 2 + 1] = make_float4(r2.x, r2.y, r3.x, r3.y);
  }
}
#undef AGGH_ONE

// ---------------- fp32 FFMA GEMM (gemm1 / gemm5) -----------------------------
template <int K, int DOUT, bool RELU, bool BIAS, bool OUTH>
__global__ void __launch_bounds__(256) gemm_kernel(
    const float* __restrict__ A, const float* __restrict__ W,
    const float* __restrict__ bias, void* __restrict__ out) {
  constexpr int COLT = (DOUT < 64) ? DOUT : 64;
  constexpr int VPT = COLT / 32;
  constexpr int KS = K + 4;
  constexpr int R = 8;
  __shared__ __align__(16) float Ws[COLT * KS];
  __shared__ __align__(16) float As[64 * KS];

  const int col0 = blockIdx.y * COLT;
  const int row0 = blockIdx.x * 64;
  const int tid = threadIdx.x;

  constexpr int CHUNKS = 64 * (K / 4);
#pragma unroll 4
  for (int c = tid; c < CHUNKS; c += 256) {
    int row = c / (K / 4), col4 = c % (K / 4);
    cp_async16(s2u(&As[row * KS + col4 * 4]), A + (size_t)(row0 + row) * K + col4 * 4);
  }
  asm volatile("cp.async.commit_group;\n");

  for (int i = tid; i < COLT * K; i += 256) {
    int k = i / COLT, c = i - k * COLT;
    Ws[c * KS + k] = __ldg(&W[k * DOUT + col0 + c]);
  }
  asm volatile("cp.async.wait_group 0;\n");
  __syncthreads();

  const int lane = tid & 31;
  const int warp = tid >> 5;

  ull acc[R][VPT];
#pragma unroll
  for (int r = 0; r < R; r++)
#pragma unroll
    for (int v = 0; v < VPT; v++) acc[r][v] = 0ull;

#pragma unroll 2
  for (int k = 0; k < K; k += 4) {
    ull w01[VPT], w23[VPT];
#pragma unroll
    for (int v = 0; v < VPT; v++) {
      float4 wv = *reinterpret_cast<const float4*>(&Ws[(lane + 32 * v) * KS + k]);
      w01[v] = reinterpret_cast<ull*>(&wv)[0];
      w23[v] = reinterpret_cast<ull*>(&wv)[1];
    }
#pragma unroll
    for (int r = 0; r < R; r++) {
      float4 av = *reinterpret_cast<const float4*>(&As[(warp * R + r) * KS + k]);
      ull a01 = reinterpret_cast<ull*>(&av)[0];
      ull a23 = reinterpret_cast<ull*>(&av)[1];
#pragma unroll
      for (int v = 0; v < VPT; v++) {
        acc[r][v] = ffma2(a01, w01[v], acc[r][v]);
        acc[r][v] = ffma2(a23, w23[v], acc[r][v]);
      }
    }
  }

#pragma unroll
  for (int r = 0; r < R; r++) {
#pragma unroll
    for (int v = 0; v < VPT; v++) {
      float s = hsum2(acc[r][v]);
      int c = col0 + lane + 32 * v;
      if (BIAS) s += __ldg(&bias[c]);
      if (RELU) s = fmaxf(s, 0.0f);
      if (OUTH)
        ((__half*)out)[(size_t)(row0 + warp * R + r) * DOUT + c] = __float2half_rn(s);
      else
        ((float*)out)[(size_t)(row0 + warp * R + r) * DOUT + c] = s;
    }
  }
}

// ---------------- HMMA fp16 GEMM (interior layers) ---------------------------
// out[N,DOUT](fp16) = A[N,K](fp16) @ W[K,DOUT](fp32->fp16) (+bias)(relu)
// 256 thr = 8 warps in a 4(row)x2(col) grid; warp tile 16 x DOUT/2.
// mma.sync m16n8k16 f32 accum; ldmatrix with +8-half row pads (16B) for
// conflict-free smem rows.
template <int K, int DOUT, bool RELU, bool BIAS>
__global__ void __launch_bounds__(256) gemm_h_kernel(
    const __half* __restrict__ A, const float* __restrict__ W,
    const float* __restrict__ bias, __half* __restrict__ out) {
  constexpr int LDA = K + 8;
  constexpr int LDB = DOUT + 8;
  extern __shared__ __align__(16) __half smh[];
  __half* As = smh;               // [64][LDA]
  __half* Ws = smh + 64 * LDA;    // [K][LDB]

  const int tid = threadIdx.x;
  const int lane = tid & 31;
  const int warp = tid >> 5;
  const int row0 = blockIdx.x * 64;

  // A tile fp16 via cp.async (16B = 8 halves per chunk)
  constexpr int RCH = K / 8;
#pragma unroll 4
  for (int c = tid; c < 64 * RCH; c += 256) {
    int r = c / RCH, cc = c % RCH;
    cp_async16(s2u(&As[r * LDA + cc * 8]), A + (size_t)(row0 + r) * K + cc * 8);
  }
  asm volatile("cp.async.commit_group;\n");

  // W fp32 -> fp16 smem [k][n], coalesced global reads
  for (int i = tid; i < K * DOUT; i += 256) {
    int k = i / DOUT, n = i - k * DOUT;
    Ws[k * LDB + n] = __float2half_rn(__ldg(&W[i]));
  }
  asm volatile("cp.async.wait_group 0;\n");
  __syncthreads();

  constexpr int SPAN = DOUT / 2;   // warp col span
  constexpr int NB = SPAN / 8;     // n8-blocks per warp (4 or 8)
  const int wr = warp & 3, wc = warp >> 2;
  const int r0 = wr * 16, n0 = wc * SPAN;

  float acc[NB][4];
#pragma unroll
  for (int nb = 0; nb < NB; nb++)
#pragma unroll
    for (int i = 0; i < 4; i++) acc[nb][i] = 0.0f;

  // ldmatrix base addresses (canonical m16n16 / k16n16 patterns)
  const uint32_t a_base = s2u(&As[(r0 + (lane & 15)) * LDA + (lane >> 4) * 8]);
  const int bt_row = ((lane >> 3) & 1) * 8 + (lane & 7);
  const int bt_col = (lane >> 4) * 8;
  const uint32_t b_base = s2u(&Ws[bt_row * LDB + n0 + bt_col]);

#pragma unroll
  for (int ks = 0; ks < K / 16; ks++) {
    uint32_t a0, a1, a2, a3;
    ldsm_x4(a0, a1, a2, a3, a_base + ks * 32);          // +16 halves along k
#pragma unroll
    for (int nb = 0; nb < NB; nb += 2) {
      uint32_t b0, b1, b2, b3;
      ldsm_x4_t(b0, b1, b2, b3,
                b_base + (uint32_t)(ks * 16 * LDB + nb * 8) * 2);
      mma16816(acc[nb], a0, a1, a2, a3, b0, b1);
      mma16816(acc[nb + 1], a0, a1, a2, a3, b2, b3);
    }
  }

  // epilogue: c-frag rows = r0 + lane/4 (+8), cols = (lane%4)*2 (+1)
  const int orow = row0 + r0 + (lane >> 2);
#pragma unroll
  for (int nb = 0; nb < NB; nb++) {
    int col = n0 + nb * 8 + (lane & 3) * 2;
    float v0 = acc[nb][0], v1 = acc[nb][1], v2 = acc[nb][2], v3 = acc[nb][3];
    if (BIAS) {
      float b0 = __ldg(&bias[col]), b1 = __ldg(&bias[col + 1]);
      v0 += b0; v1 += b1; v2 += b0; v3 += b1;
    }
    if (RELU) {
      v0 = fmaxf(v0, 0.f); v1 = fmaxf(v1, 0.f);
      v2 = fmaxf(v2, 0.f); v3 = fmaxf(v3, 0.f);
    }
    __half2 h01 = __floats2half2_rn(v0, v1);
    __half2 h23 = __floats2half2_rn(v2, v3);
    *reinterpret_cast<__half2*>(&out[(size_t)orow * DOUT + col]) = h01;
    *reinterpret_cast<__half2*>(&out[(size_t)(orow + 8) * DOUT + col]) = h23;
  }
}

// ---------------- launch ------------------------------------------------------
extern "C" void kernel_launch(void* const* d_in, const int* in_sizes, int n_in,
                              void* d_out, int out_size) {
  (void)in_sizes; (void)n_in; (void)out_size;
  const float* x  = (const float*)d_in[0];
  const int*   ei = (const int*)d_in[1];
  const int* src = ei;
  const int* dst = ei + EE;
  const float* W1 = (const float*)d_in[3];
  const float* b1 = (const float*)d_in[4];
  const float* W2 = (const float*)d_in[5];
  const float* b2 = (const float*)d_in[6];
  const float* W3 = (const float*)d_in[7];
  const float* b3 = (const float*)d_in[8];
  const float* W4 = (const float*)d_in[9];
  const float* b4 = (const float*)d_in[10];
  const float* Wl = (const float*)d_in[11];
  const float* bl = (const float*)d_in[12];
  float* out = (float*)d_out;

  float* buf0;
  __half *hbuf0, *hbuf1;
  cudaGetSymbolAddress((void**)&buf0, g_buf0);
  cudaGetSymbolAddress((void**)&hbuf0, g_hbuf0);
  cudaGetSymbolAddress((void**)&hbuf1, g_hbuf1);

  // dynamic smem sizes for the HMMA gemms
  const int SM23 = (64 * (64 + 8) + 64 * (128 + 8)) * 2;    // K=64,D=128
  const int SM33 = (64 * (128 + 8) + 128 * (128 + 8)) * 2;  // K=128,D=128
  const int SM34 = (64 * (128 + 8) + 128 * (64 + 8)) * 2;   // K=128,D=64

  static cudaStream_t s_prep = nullptr;
  static cudaEvent_t ev_fork = nullptr, ev_join = nullptr;
  if (s_prep == nullptr) {
    cudaStreamCreateWithFlags(&s_prep, cudaStreamNonBlocking);
    cudaEventCreateWithFlags(&ev_fork, cudaEventDisableTiming);
    cudaEventCreateWithFlags(&ev_join, cudaEventDisableTiming);
    cudaFuncSetAttribute(gemm_h_kernel<128, 128, false, false>,
                         cudaFuncAttributeMaxDynamicSharedMemorySize, SM33);
    cudaFuncSetAttribute(gemm_h_kernel<64, 128, true, true>,
                         cudaFuncAttributeMaxDynamicSharedMemorySize, SM23);
    cudaFuncSetAttribute(gemm_h_kernel<128, 64, false, false>,
                         cudaFuncAttributeMaxDynamicSharedMemorySize, SM34);
  }

  // ---- fork: CSR prep on s_prep, concurrent with gemm1 on the main stream.
  cudaEventRecord(ev_fork, 0);
  cudaStreamWaitEvent(s_prep, ev_fork, 0);

  count_deg_kernel<<<(EE + 255) / 256, 256, 0, s_prep>>>(dst);
  scan_fused_kernel<<<NSCAN_BLK, 256, 0, s_prep>>>();
  fill_csr_kernel<<<(NNZ + 255) / 256, 256, 0, s_prep>>>(src, dst);
  cudaEventRecord(ev_join, s_prep);

  const int GEMM_BLOCKS = NN / 64;      // 625
  const int AGGH64_BLOCKS = NN / 32;    // 1250 (8 lanes/node)
  const int AGGH128_BLOCKS = NN / 16;   // 2500 (16 lanes/node)

  // L1 GEMM overlaps prep: t = x @ W1 -> fp16
  gemm_kernel<128, 64, false, false, true>
      <<<dim3(GEMM_BLOCKS, 1), 256>>>(x, W1, nullptr, hbuf0);

  cudaStreamWaitEvent(0, ev_join, 0);  // join: aggs need the CSR

  // h1 = relu(agg(t) + b1) -> fp16
  aggh_kernel<64, true, true, true><<<AGGH64_BLOCKS, 256>>>(hbuf0, b1, hbuf1);
  // a = agg(h1) -> fp16 (feeds HMMA gemm)
  aggh_kernel<64, false, false, true><<<AGGH64_BLOCKS, 256>>>(hbuf1, nullptr, hbuf0);
  // h2 = relu(a @ W2 + b2) -> fp16   [HMMA]
  gemm_h_kernel<64, 128, true, true>
      <<<GEMM_BLOCKS, 256, SM23>>>(hbuf0, W2, b2, hbuf1);
  // t3 = h2 @ W3 -> fp16             [HMMA]
  gemm_h_kernel<128, 128, false, false>
      <<<GEMM_BLOCKS, 256, SM33>>>(hbuf1, W3, nullptr, hbuf0);
  // h3 = relu(agg(t3) + b3) -> fp16
  aggh_kernel<128, true, true, true><<<AGGH128_BLOCKS, 256>>>(hbuf0, b3, hbuf1);
  // t4 = h3 @ W4 -> fp16             [HMMA]
  gemm_h_kernel<128, 64, false, false>
      <<<GEMM_BLOCKS, 256, SM34>>>(hbuf1, W4, nullptr, hbuf0);
  // h4 = relu(agg(t4) + b4) -> fp32
  aggh_kernel<64, true, true, false><<<AGGH64_BLOCKS, 256>>>(hbuf0, b4, buf0);
  // Head: out = h4 @ Wl + bl -> fp32 [FFMA]
  gemm_kernel<64, 32, false, true, false>
      <<<dim3(GEMM_BLOCKS, 1), 256>>>(buf0, Wl, bl, out);
}

// round 13
// speedup vs baseline: 2.0868x; 1.0724x over previous
#include <cuda_runtime.h>
#include <cuda_fp16.h>
#include <cstdint>

#define NN  40000
#define EE  640000
#define NNZ (EE + NN)   // 680000 (edges + self-loops)

#define NSCAN_BLK 40
#define SCAN_CH   1000
#define NBINS 64

typedef unsigned long long ull;

// ---------------- scratch (device globals — no runtime allocation) ----------
__device__ __align__(256) float  g_buf0[NN * 128];
__device__ __align__(256) __half g_hbuf0[NN * 128];
__device__ __align__(256) __half g_hbuf1[NN * 128];
__device__ float g_dinv[NN];
__device__ int   g_deg[NN];          // zero at load; scan re-zeroes after read
__device__ int   g_rowptr[NN + 1];
__device__ int   g_cursor[NN];
__device__ int   g_order[NN];        // nodes sorted by degree (counting sort)
__device__ int   g_hist[NBINS];      // zero at load; binscan re-zeroes
__device__ int   g_binoff[NBINS];    // rewritten fresh each replay
__device__ __align__(16) int2 g_adj[NNZ];   // {col, bitcast(weight)}
__device__ volatile int g_scan_flag[NSCAN_BLK];
__device__ volatile int g_scan_pref[NSCAN_BLK];

// ---------------- helpers -----------------------------------------------------
__device__ __forceinline__ ull ffma2(ull a, ull b, ull c) {
  ull d;
  asm("fma.rn.f32x2 %0, %1, %2, %3;" : "=l"(d) : "l"(a), "l"(b), "l"(c));
  return d;
}
__device__ __forceinline__ float hsum2(ull v) {
  float lo, hi;
  asm("mov.b64 {%0, %1}, %2;" : "=f"(lo), "=f"(hi) : "l"(v));
  return lo + hi;
}
__device__ __forceinline__ ull pack2(float lo, float hi) {
  ull v;
  asm("mov.b64 %0, {%1, %2};" : "=l"(v) : "f"(lo), "f"(hi));
  return v;
}
__device__ __forceinline__ ull h2ull(uint32_t h) {  // half2 -> packed float2
  __half2 hh = *reinterpret_cast<__half2*>(&h);
  float2 f = __half22float2(hh);
  return *reinterpret_cast<ull*>(&f);
}
__device__ __forceinline__ float2 u2f2(ull v) {
  return *reinterpret_cast<float2*>(&v);
}
__device__ __forceinline__ void cp_async16(uint32_t saddr, const void* gaddr) {
  asm volatile("cp.async.cg.shared.global [%0], [%1], 16;\n"
               :: "r"(saddr), "l"(gaddr));
}
__device__ __forceinline__ uint32_t s2u(const void* p) {
  return (uint32_t)__cvta_generic_to_shared(p);
}
__device__ __forceinline__ void ldsm_x4(uint32_t& r0, uint32_t& r1,
                                        uint32_t& r2, uint32_t& r3, uint32_t a) {
  asm volatile("ldmatrix.sync.aligned.m8n8.x4.shared.b16 {%0,%1,%2,%3}, [%4];"
               : "=r"(r0), "=r"(r1), "=r"(r2), "=r"(r3) : "r"(a));
}
__device__ __forceinline__ void ldsm_x4_t(uint32_t& r0, uint32_t& r1,
                                          uint32_t& r2, uint32_t& r3, uint32_t a) {
  asm volatile("ldmatrix.sync.aligned.m8n8.x4.trans.shared.b16 {%0,%1,%2,%3}, [%4];"
               : "=r"(r0), "=r"(r1), "=r"(r2), "=r"(r3) : "r"(a));
}
__device__ __forceinline__ void mma16816(float* c, uint32_t a0, uint32_t a1,
                                         uint32_t a2, uint32_t a3,
                                         uint32_t b0, uint32_t b1) {
  asm volatile(
      "mma.sync.aligned.m16n8k16.row.col.f32.f16.f16.f32 "
      "{%0,%1,%2,%3}, {%4,%5,%6,%7}, {%8,%9}, {%0,%1,%2,%3};"
      : "+f"(c[0]), "+f"(c[1]), "+f"(c[2]), "+f"(c[3])
      : "r"(a0), "r"(a1), "r"(a2), "r"(a3), "r"(b0), "r"(b1));
}

// ---------------- preprocessing ---------------------------------------------
__global__ void count_deg_kernel(const int* __restrict__ dst) {
  int e = blockIdx.x * 256 + threadIdx.x;
  if (e < EE) atomicAdd(&g_deg[dst[e]], 1);
}

// Exclusive scan of (deg+1) via decoupled lookback; also computes dinv,
// re-zeroes g_deg, and accumulates a degree histogram for the node sort.
__global__ void __launch_bounds__(256) scan_fused_kernel() {
  __shared__ int warp_pref[8];
  __shared__ int s_base;
  __shared__ int shist[NBINS];
  const int b = blockIdx.x, t = threadIdx.x;
  const int lane = t & 31, warp = t >> 5;
  if (t < NBINS) shist[t] = 0;

  int v[4];
  int s = 0;
#pragma unroll
  for (int i = 0; i < 4; i++) {
    int li = t * 4 + i;
    int d1 = 0;
    if (li < SCAN_CH) {
      int idx = b * SCAN_CH + li;
      d1 = g_deg[idx] + 1;
      g_deg[idx] = 0;
      g_dinv[idx] = rsqrtf((float)d1);
      atomicAdd(&shist[min(d1, NBINS - 1)], 1);
    }
    v[i] = s;
    s += d1;
  }
  int ws = s;
#pragma unroll
  for (int off = 1; off < 32; off <<= 1) {
    int u = __shfl_up_sync(0xffffffffu, ws, off);
    if (lane >= off) ws += u;
  }
  if (lane == 31) warp_pref[warp] = ws;
  __syncthreads();
  if (t < NBINS && shist[t]) atomicAdd(&g_hist[t], shist[t]);
  if (t == 0) {
    int run = 0;
#pragma unroll
    for (int i = 0; i < 8; i++) { int x = warp_pref[i]; warp_pref[i] = run; run += x; }
    int pref = 0;
    if (b > 0) {
      while (g_scan_flag[b - 1] == 0) {}
      __threadfence();
      pref = g_scan_pref[b - 1];
      g_scan_flag[b - 1] = 0;
    }
    if (b < NSCAN_BLK - 1) {
      g_scan_pref[b] = pref + run;
      __threadfence();
      g_scan_flag[b] = 1;
    } else {
      g_rowptr[NN] = pref + run;
    }
    s_base = pref;
  }
  __syncthreads();
  const int base = s_base + warp_pref[warp] + (ws - s);
#pragma unroll
  for (int i = 0; i < 4; i++) {
    int li = t * 4 + i;
    if (li < SCAN_CH) {
      int idx = b * SCAN_CH + li;
      int p = base + v[i];
      g_rowptr[idx] = p;
      g_cursor[idx] = p;
    }
  }
}

// Scan the degree histogram into bin offsets; reset hist for the next replay.
__global__ void binscan_kernel() {
  __shared__ int sh[NBINS];
  const int t = threadIdx.x;
  sh[t] = g_hist[t];
  g_hist[t] = 0;
  __syncthreads();
  for (int off = 1; off < NBINS; off <<= 1) {
    int u = (t >= off) ? sh[t - off] : 0;
    __syncthreads();
    sh[t] += u;
    __syncthreads();
  }
  g_binoff[t] = (t == 0) ? 0 : sh[t - 1];
}

// Scatter nodes into degree-sorted order (binoff rewritten fresh each replay).
__global__ void sort_scatter_kernel() {
  int i = blockIdx.x * 256 + threadIdx.x;
  if (i < NN) {
    int d1 = g_rowptr[i + 1] - g_rowptr[i];
    int pos = atomicAdd(&g_binoff[min(d1, NBINS - 1)], 1);
    g_order[pos] = i;
  }
}

__global__ void fill_csr_kernel(const int* __restrict__ src,
                                const int* __restrict__ dst) {
  int t = blockIdx.x * 256 + threadIdx.x;
  if (t < EE) {
    int s = src[t], d = dst[t];
    int pos = atomicAdd(&g_cursor[d], 1);
    g_adj[pos] = make_int2(s, __float_as_int(g_dinv[s] * g_dinv[d]));
  } else if (t < NNZ) {
    int i = t - EE;
    int pos = atomicAdd(&g_cursor[i], 1);
    float di = g_dinv[i];
    g_adj[pos] = make_int2(i, __float_as_int(di * di));
  }
}

// ---------------- fp16-input aggregation (degree-sorted, unroll 8) -----------
#define AGGH_ONE(cx, wy)                                                       \
  {                                                                            \
    uint4 xx = __ldg(reinterpret_cast<const uint4*>(Hin + (size_t)(cx) * D) + sub); \
    ull ww = pack2(__int_as_float(wy), __int_as_float(wy));                    \
    a0 = ffma2(h2ull(xx.x), ww, a0);                                           \
    a1 = ffma2(h2ull(xx.y), ww, a1);                                           \
    a2 = ffma2(h2ull(xx.z), ww, a2);                                           \
    a3 = ffma2(h2ull(xx.w), ww, a3);                                           \
  }
#define AGGH_Q(q)                                                              \
  {                                                                            \
    uint4 xa = __ldg(reinterpret_cast<const uint4*>(Hin + (size_t)(q).x * D) + sub); \
    uint4 xb = __ldg(reinterpret_cast<const uint4*>(Hin + (size_t)(q).z * D) + sub); \
    ull wa = pack2(__int_as_float((q).y), __int_as_float((q).y));              \
    ull wb = pack2(__int_as_float((q).w), __int_as_float((q).w));              \
    a0 = ffma2(h2ull(xa.x), wa, a0);                                           \
    a1 = ffma2(h2ull(xa.y), wa, a1);                                           \
    a2 = ffma2(h2ull(xa.z), wa, a2);                                           \
    a3 = ffma2(h2ull(xa.w), wa, a3);                                           \
    a0 = ffma2(h2ull(xb.x), wb, a0);                                           \
    a1 = ffma2(h2ull(xb.y), wb, a1);                                           \
    a2 = ffma2(h2ull(xb.z), wb, a2);                                           \
    a3 = ffma2(h2ull(xb.w), wb, a3);                                           \
  }

template <int D, bool RELU, bool BIAS, bool OUTH>
__global__ void __launch_bounds__(256) aggh_kernel(
    const __half* __restrict__ Hin, const float* __restrict__ bias,
    void* __restrict__ Hout) {
  constexpr int LANES = D / 8;
  const int slot = blockIdx.x * (256 / LANES) + threadIdx.x / LANES;
  const int node = __ldg(&g_order[slot]);   // degree-sorted: warp-mates match
  const int sub = threadIdx.x % LANES;
  int e = g_rowptr[node];
  const int end = g_rowptr[node + 1];

  ull a0 = 0ull, a1 = 0ull, a2 = 0ull, a3 = 0ull;
  if ((e & 1) && e < end) {
    int2 av = __ldg(&g_adj[e]);
    AGGH_ONE(av.x, av.y);
    e++;
  }
  for (; e + 8 <= end; e += 8) {
    int4 q0 = __ldg(reinterpret_cast<const int4*>(g_adj + e));
    int4 q1 = __ldg(reinterpret_cast<const int4*>(g_adj + e + 2));
    int4 q2 = __ldg(reinterpret_cast<const int4*>(g_adj + e + 4));
    int4 q3 = __ldg(reinterpret_cast<const int4*>(g_adj + e + 6));
    AGGH_Q(q0);
    AGGH_Q(q1);
    AGGH_Q(q2);
    AGGH_Q(q3);
  }
  for (; e + 2 <= end; e += 2) {
    int4 q = __ldg(reinterpret_cast<const int4*>(g_adj + e));
    AGGH_Q(q);
  }
  if (e < end) {
    int2 av = __ldg(&g_adj[e]);
    AGGH_ONE(av.x, av.y);
  }

  float2 r0 = u2f2(a0), r1 = u2f2(a1), r2 = u2f2(a2), r3 = u2f2(a3);
  if (BIAS) {
    float4 b0 = __ldg(reinterpret_cast<const float4*>(bias) + sub * 2);
    float4 b1 = __ldg(reinterpret_cast<const float4*>(bias) + sub * 2 + 1);
    r0.x += b0.x; r0.y += b0.y; r1.x += b0.z; r1.y += b0.w;
    r2.x += b1.x; r2.y += b1.y; r3.x += b1.z; r3.y += b1.w;
  }
  if (RELU) {
    r0.x = fmaxf(r0.x, 0.f); r0.y = fmaxf(r0.y, 0.f);
    r1.x = fmaxf(r1.x, 0.f); r1.y = fmaxf(r1.y, 0.f);
    r2.x = fmaxf(r2.x, 0.f); r2.y = fmaxf(r2.y, 0.f);
    r3.x = fmaxf(r3.x, 0.f); r3.y = fmaxf(r3.y, 0.f);
  }
  if (OUTH) {
    uint4 o;
    __half2 h0 = __floats2half2_rn(r0.x, r0.y);
    __half2 h1 = __floats2half2_rn(r1.x, r1.y);
    __half2 h2 = __floats2half2_rn(r2.x, r2.y);
    __half2 h3 = __floats2half2_rn(r3.x, r3.y);
    o.x = *reinterpret_cast<uint32_t*>(&h0);
    o.y = *reinterpret_cast<uint32_t*>(&h1);
    o.z = *reinterpret_cast<uint32_t*>(&h2);
    o.w = *reinterpret_cast<uint32_t*>(&h3);
    reinterpret_cast<uint4*>((__half*)Hout + (size_t)node * D)[sub] = o;
  } else {
    float4* orow = reinterpret_cast<float4*>((float*)Hout + (size_t)node * D);
    orow[sub * 2] = make_float4(r0.x, r0.y, r1.x, r1.y);
    orow[sub * 2 + 1] = make_float4(r2.x, r2.y, r3.x, r3.y);
  }
}
#undef AGGH_ONE
#undef AGGH_Q

// ---------------- fp32 FFMA GEMM (gemm1 / gemm5) -----------------------------
template <int K, int DOUT, bool RELU, bool BIAS, bool OUTH>
__global__ void __launch_bounds__(256) gemm_kernel(
    const float* __restrict__ A, const float* __restrict__ W,
    const float* __restrict__ bias, void* __restrict__ out) {
  constexpr int COLT = (DOUT < 64) ? DOUT : 64;
  constexpr int VPT = COLT / 32;
  constexpr int KS = K + 4;
  constexpr int R = 8;
  __shared__ __align__(16) float Ws[COLT * KS];
  __shared__ __align__(16) float As[64 * KS];

  const int col0 = blockIdx.y * COLT;
  const int row0 = blockIdx.x * 64;
  const int tid = threadIdx.x;

  constexpr int CHUNKS = 64 * (K / 4);
#pragma unroll 4
  for (int c = tid; c < CHUNKS; c += 256) {
    int row = c / (K / 4), col4 = c % (K / 4);
    cp_async16(s2u(&As[row * KS + col4 * 4]), A + (size_t)(row0 + row) * K + col4 * 4);
  }
  asm volatile("cp.async.commit_group;\n");

  for (int i = tid; i < COLT * K; i += 256) {
    int k = i / COLT, c = i - k * COLT;
    Ws[c * KS + k] = __ldg(&W[k * DOUT + col0 + c]);
  }
  asm volatile("cp.async.wait_group 0;\n");
  __syncthreads();

  const int lane = tid & 31;
  const int warp = tid >> 5;

  ull acc[R][VPT];
#pragma unroll
  for (int r = 0; r < R; r++)
#pragma unroll
    for (int v = 0; v < VPT; v++) acc[r][v] = 0ull;

#pragma unroll 2
  for (int k = 0; k < K; k += 4) {
    ull w01[VPT], w23[VPT];
#pragma unroll
    for (int v = 0; v < VPT; v++) {
      float4 wv = *reinterpret_cast<const float4*>(&Ws[(lane + 32 * v) * KS + k]);
      w01[v] = reinterpret_cast<ull*>(&wv)[0];
      w23[v] = reinterpret_cast<ull*>(&wv)[1];
    }
#pragma unroll
    for (int r = 0; r < R; r++) {
      float4 av = *reinterpret_cast<const float4*>(&As[(warp * R + r) * KS + k]);
      ull a01 = reinterpret_cast<ull*>(&av)[0];
      ull a23 = reinterpret_cast<ull*>(&av)[1];
#pragma unroll
      for (int v = 0; v < VPT; v++) {
        acc[r][v] = ffma2(a01, w01[v], acc[r][v]);
        acc[r][v] = ffma2(a23, w23[v], acc[r][v]);
      }
    }
  }

#pragma unroll
  for (int r = 0; r < R; r++) {
#pragma unroll
    for (int v = 0; v < VPT; v++) {
      float s = hsum2(acc[r][v]);
      int c = col0 + lane + 32 * v;
      if (BIAS) s += __ldg(&bias[c]);
      if (RELU) s = fmaxf(s, 0.0f);
      if (OUTH)
        ((__half*)out)[(size_t)(row0 + warp * R + r) * DOUT + c] = __float2half_rn(s);
      else
        ((float*)out)[(size_t)(row0 + warp * R + r) * DOUT + c] = s;
    }
  }
}

// ---------------- HMMA fp16 GEMM (interior layers) ---------------------------
template <int K, int DOUT, bool RELU, bool BIAS>
__global__ void __launch_bounds__(256) gemm_h_kernel(
    const __half* __restrict__ A, const float* __restrict__ W,
    const float* __restrict__ bias, __half* __restrict__ out) {
  constexpr int LDA = K + 8;
  constexpr int LDB = DOUT + 8;
  extern __shared__ __align__(16) __half smh[];
  __half* As = smh;               // [64][LDA]
  __half* Ws = smh + 64 * LDA;    // [K][LDB]

  const int tid = threadIdx.x;
  const int lane = tid & 31;
  const int warp = tid >> 5;
  const int row0 = blockIdx.x * 64;

  constexpr int RCH = K / 8;
#pragma unroll 4
  for (int c = tid; c < 64 * RCH; c += 256) {
    int r = c / RCH, cc = c % RCH;
    cp_async16(s2u(&As[r * LDA + cc * 8]), A + (size_t)(row0 + r) * K + cc * 8);
  }
  asm volatile("cp.async.commit_group;\n");

  for (int i = tid; i < K * DOUT; i += 256) {
    int k = i / DOUT, n = i - k * DOUT;
    Ws[k * LDB + n] = __float2half_rn(__ldg(&W[i]));
  }
  asm volatile("cp.async.wait_group 0;\n");
  __syncthreads();

  constexpr int SPAN = DOUT / 2;
  constexpr int NB = SPAN / 8;
  const int wr = warp & 3, wc = warp >> 2;
  const int r0 = wr * 16, n0 = wc * SPAN;

  float acc[NB][4];
#pragma unroll
  for (int nb = 0; nb < NB; nb++)
#pragma unroll
    for (int i = 0; i < 4; i++) acc[nb][i] = 0.0f;

  const uint32_t a_base = s2u(&As[(r0 + (lane & 15)) * LDA + (lane >> 4) * 8]);
  const int bt_row = ((lane >> 3) & 1) * 8 + (lane & 7);
  const int bt_col = (lane >> 4) * 8;
  const uint32_t b_base = s2u(&Ws[bt_row * LDB + n0 + bt_col]);

#pragma unroll
  for (int ks = 0; ks < K / 16; ks++) {
    uint32_t a0, a1, a2, a3;
    ldsm_x4(a0, a1, a2, a3, a_base + ks * 32);
#pragma unroll
    for (int nb = 0; nb < NB; nb += 2) {
      uint32_t b0, b1, b2, b3;
      ldsm_x4_t(b0, b1, b2, b3,
                b_base + (uint32_t)(ks * 16 * LDB + nb * 8) * 2);
      mma16816(acc[nb], a0, a1, a2, a3, b0, b1);
      mma16816(acc[nb + 1], a0, a1, a2, a3, b2, b3);
    }
  }

  const int orow = row0 + r0 + (lane >> 2);
#pragma unroll
  for (int nb = 0; nb < NB; nb++) {
    int col = n0 + nb * 8 + (lane & 3) * 2;
    float v0 = acc[nb][0], v1 = acc[nb][1], v2 = acc[nb][2], v3 = acc[nb][3];
    if (BIAS) {
      float b0 = __ldg(&bias[col]), b1 = __ldg(&bias[col + 1]);
      v0 += b0; v1 += b1; v2 += b0; v3 += b1;
    }
    if (RELU) {
      v0 = fmaxf(v0, 0.f); v1 = fmaxf(v1, 0.f);
      v2 = fmaxf(v2, 0.f); v3 = fmaxf(v3, 0.f);
    }
    __half2 h01 = __floats2half2_rn(v0, v1);
    __half2 h23 = __floats2half2_rn(v2, v3);
    *reinterpret_cast<__half2*>(&out[(size_t)orow * DOUT + col]) = h01;
    *reinterpret_cast<__half2*>(&out[(size_t)(orow + 8) * DOUT + col]) = h23;
  }
}

// ---------------- launch ------------------------------------------------------
extern "C" void kernel_launch(void* const* d_in, const int* in_sizes, int n_in,
                              void* d_out, int out_size) {
  (void)in_sizes; (void)n_in; (void)out_size;
  const float* x  = (const float*)d_in[0];
  const int*   ei = (const int*)d_in[1];
  const int* src = ei;
  const int* dst = ei + EE;
  const float* W1 = (const float*)d_in[3];
  const float* b1 = (const float*)d_in[4];
  const float* W2 = (const float*)d_in[5];
  const float* b2 = (const float*)d_in[6];
  const float* W3 = (const float*)d_in[7];
  const float* b3 = (const float*)d_in[8];
  const float* W4 = (const float*)d_in[9];
  const float* b4 = (const float*)d_in[10];
  const float* Wl = (const float*)d_in[11];
  const float* bl = (const float*)d_in[12];
  float* out = (float*)d_out;

  float* buf0;
  __half *hbuf0, *hbuf1;
  cudaGetSymbolAddress((void**)&buf0, g_buf0);
  cudaGetSymbolAddress((void**)&hbuf0, g_hbuf0);
  cudaGetSymbolAddress((void**)&hbuf1, g_hbuf1);

  const int SM23 = (64 * (64 + 8) + 64 * (128 + 8)) * 2;
  const int SM33 = (64 * (128 + 8) + 128 * (128 + 8)) * 2;
  const int SM34 = (64 * (128 + 8) + 128 * (64 + 8)) * 2;

  static cudaStream_t s_prep = nullptr;
  static cudaEvent_t ev_fork = nullptr, ev_join = nullptr;
  if (s_prep == nullptr) {
    cudaStreamCreateWithFlags(&s_prep, cudaStreamNonBlocking);
    cudaEventCreateWithFlags(&ev_fork, cudaEventDisableTiming);
    cudaEventCreateWithFlags(&ev_join, cudaEventDisableTiming);
    cudaFuncSetAttribute(gemm_h_kernel<128, 128, false, false>,
                         cudaFuncAttributeMaxDynamicSharedMemorySize, SM33);
    cudaFuncSetAttribute(gemm_h_kernel<64, 128, true, true>,
                         cudaFuncAttributeMaxDynamicSharedMemorySize, SM23);
    cudaFuncSetAttribute(gemm_h_kernel<128, 64, false, false>,
                         cudaFuncAttributeMaxDynamicSharedMemorySize, SM34);
  }

  // ---- fork: CSR prep + degree sort on s_prep, overlapped with gemm1.
  cudaEventRecord(ev_fork, 0);
  cudaStreamWaitEvent(s_prep, ev_fork, 0);

  count_deg_kernel<<<(EE + 255) / 256, 256, 0, s_prep>>>(dst);
  scan_fused_kernel<<<NSCAN_BLK, 256, 0, s_prep>>>();
  binscan_kernel<<<1, NBINS, 0, s_prep>>>();
  sort_scatter_kernel<<<(NN + 255) / 256, 256, 0, s_prep>>>();
  fill_csr_kernel<<<(NNZ + 255) / 256, 256, 0, s_prep>>>(src, dst);
  cudaEventRecord(ev_join, s_prep);

  const int GEMM_BLOCKS = NN / 64;      // 625
  const int AGGH64_BLOCKS = NN / 32;    // 1250 (8 lanes/node)
  const int AGGH128_BLOCKS = NN / 16;   // 2500 (16 lanes/node)

  // L1 GEMM overlaps prep: t = x @ W1 -> fp16
  gemm_kernel<128, 64, false, false, true>
      <<<dim3(GEMM_BLOCKS, 1), 256>>>(x, W1, nullptr, hbuf0);

  cudaStreamWaitEvent(0, ev_join, 0);  // join: aggs need CSR + order

  // h1 = relu(agg(t) + b1) -> fp16
  aggh_kernel<64, true, true, true><<<AGGH64_BLOCKS, 256>>>(hbuf0, b1, hbuf1);
  // a = agg(h1) -> fp16
  aggh_kernel<64, false, false, true><<<AGGH64_BLOCKS, 256>>>(hbuf1, nullptr, hbuf0);
  // h2 = relu(a @ W2 + b2) -> fp16   [HMMA]
  gemm_h_kernel<64, 128, true, true>
      <<<GEMM_BLOCKS, 256, SM23>>>(hbuf0, W2, b2, hbuf1);
  // t3 = h2 @ W3 -> fp16             [HMMA]
  gemm_h_kernel<128, 128, false, false>
      <<<GEMM_BLOCKS, 256, SM33>>>(hbuf1, W3, nullptr, hbuf0);
  // h3 = relu(agg(t3) + b3) -> fp16
  aggh_kernel<128, true, true, true><<<AGGH128_BLOCKS, 256>>>(hbuf0, b3, hbuf1);
  // t4 = h3 @ W4 -> fp16             [HMMA]
  gemm_h_kernel<128, 64, false, false>
      <<<GEMM_BLOCKS, 256, SM34>>>(hbuf1, W4, nullptr, hbuf0);
  // h4 = relu(agg(t4) + b4) -> fp32
  aggh_kernel<64, true, true, false><<<AGGH64_BLOCKS, 256>>>(hbuf0, b4, buf0);
  // Head: out = h4 @ Wl + bl -> fp32 [FFMA]
  gemm_kernel<64, 32, false, true, false>
      <<<dim3(GEMM_BLOCKS, 1), 256>>>(buf0, Wl, bl, out);
}

// round 14
// speedup vs baseline: 2.1191x; 1.0155x over previous
#include <cuda_runtime.h>
#include <cuda_fp16.h>
#include <cstdint>

#define NN  40000
#define EE  640000
#define NNZ (EE + NN)   // 680000 (edges + self-loops)

#define NSCAN_BLK 40
#define SCAN_CH   1000
#define NBINS 64

typedef unsigned long long ull;

// ---------------- scratch (device globals — no runtime allocation) ----------
__device__ __align__(256) float  g_buf0[NN * 128];
__device__ __align__(256) __half g_hbuf0[NN * 128];
__device__ __align__(256) __half g_hbuf1[NN * 128];
__device__ float g_dinv[NN];
__device__ int   g_deg[NN];          // zero at load; scan re-zeroes after read
__device__ int   g_rowptr[NN + 1];
__device__ int   g_cursor[NN];
__device__ int   g_order[NN];        // nodes sorted by degree (counting sort)
__device__ int   g_hist[NBINS];      // zero at load; binscan re-zeroes
__device__ int   g_binoff[NBINS];    // rewritten fresh each replay
__device__ __align__(16) int2 g_adj[NNZ];   // {col, bitcast(weight)}
__device__ volatile int g_scan_flag[NSCAN_BLK];
__device__ volatile int g_scan_pref[NSCAN_BLK];

// ---------------- helpers -----------------------------------------------------
__device__ __forceinline__ ull ffma2(ull a, ull b, ull c) {
  ull d;
  asm("fma.rn.f32x2 %0, %1, %2, %3;" : "=l"(d) : "l"(a), "l"(b), "l"(c));
  return d;
}
__device__ __forceinline__ float hsum2(ull v) {
  float lo, hi;
  asm("mov.b64 {%0, %1}, %2;" : "=f"(lo), "=f"(hi) : "l"(v));
  return lo + hi;
}
__device__ __forceinline__ ull pack2(float lo, float hi) {
  ull v;
  asm("mov.b64 %0, {%1, %2};" : "=l"(v) : "f"(lo), "f"(hi));
  return v;
}
__device__ __forceinline__ ull h2ull(uint32_t h) {  // half2 -> packed float2
  __half2 hh = *reinterpret_cast<__half2*>(&h);
  float2 f = __half22float2(hh);
  return *reinterpret_cast<ull*>(&f);
}
__device__ __forceinline__ float2 u2f2(ull v) {
  return *reinterpret_cast<float2*>(&v);
}
__device__ __forceinline__ void cp_async16(uint32_t saddr, const void* gaddr) {
  asm volatile("cp.async.cg.shared.global [%0], [%1], 16;\n"
               :: "r"(saddr), "l"(gaddr));
}
__device__ __forceinline__ uint32_t s2u(const void* p) {
  return (uint32_t)__cvta_generic_to_shared(p);
}
__device__ __forceinline__ void ldsm_x4(uint32_t& r0, uint32_t& r1,
                                        uint32_t& r2, uint32_t& r3, uint32_t a) {
  asm volatile("ldmatrix.sync.aligned.m8n8.x4.shared.b16 {%0,%1,%2,%3}, [%4];"
               : "=r"(r0), "=r"(r1), "=r"(r2), "=r"(r3) : "r"(a));
}
__device__ __forceinline__ void ldsm_x4_t(uint32_t& r0, uint32_t& r1,
                                          uint32_t& r2, uint32_t& r3, uint32_t a) {
  asm volatile("ldmatrix.sync.aligned.m8n8.x4.trans.shared.b16 {%0,%1,%2,%3}, [%4];"
               : "=r"(r0), "=r"(r1), "=r"(r2), "=r"(r3) : "r"(a));
}
__device__ __forceinline__ void mma16816(float* c, uint32_t a0, uint32_t a1,
                                         uint32_t a2, uint32_t a3,
                                         uint32_t b0, uint32_t b1) {
  asm volatile(
      "mma.sync.aligned.m16n8k16.row.col.f32.f16.f16.f32 "
      "{%0,%1,%2,%3}, {%4,%5,%6,%7}, {%8,%9}, {%0,%1,%2,%3};"
      : "+f"(c[0]), "+f"(c[1]), "+f"(c[2]), "+f"(c[3])
      : "r"(a0), "r"(a1), "r"(a2), "r"(a3), "r"(b0), "r"(b1));
}

// ---------------- preprocessing ---------------------------------------------
__global__ void count_deg_kernel(const int* __restrict__ dst) {
  int e = blockIdx.x * 256 + threadIdx.x;
  if (e < EE) atomicAdd(&g_deg[dst[e]], 1);
}

// Exclusive scan of (deg+1) via decoupled lookback; also computes dinv,
// re-zeroes g_deg, and accumulates a degree histogram for the node sort.
__global__ void __launch_bounds__(256) scan_fused_kernel() {
  __shared__ int warp_pref[8];
  __shared__ int s_base;
  __shared__ int shist[NBINS];
  const int b = blockIdx.x, t = threadIdx.x;
  const int lane = t & 31, warp = t >> 5;
  if (t < NBINS) shist[t] = 0;

  int v[4];
  int s = 0;
#pragma unroll
  for (int i = 0; i < 4; i++) {
    int li = t * 4 + i;
    int d1 = 0;
    if (li < SCAN_CH) {
      int idx = b * SCAN_CH + li;
      d1 = g_deg[idx] + 1;
      g_deg[idx] = 0;
      g_dinv[idx] = rsqrtf((float)d1);
      atomicAdd(&shist[min(d1, NBINS - 1)], 1);
    }
    v[i] = s;
    s += d1;
  }
  int ws = s;
#pragma unroll
  for (int off = 1; off < 32; off <<= 1) {
    int u = __shfl_up_sync(0xffffffffu, ws, off);
    if (lane >= off) ws += u;
  }
  if (lane == 31) warp_pref[warp] = ws;
  __syncthreads();
  if (t < NBINS && shist[t]) atomicAdd(&g_hist[t], shist[t]);
  if (t == 0) {
    int run = 0;
#pragma unroll
    for (int i = 0; i < 8; i++) { int x = warp_pref[i]; warp_pref[i] = run; run += x; }
    int pref = 0;
    if (b > 0) {
      while (g_scan_flag[b - 1] == 0) {}
      __threadfence();
      pref = g_scan_pref[b - 1];
      g_scan_flag[b - 1] = 0;
    }
    if (b < NSCAN_BLK - 1) {
      g_scan_pref[b] = pref + run;
      __threadfence();
      g_scan_flag[b] = 1;
    } else {
      g_rowptr[NN] = pref + run;
    }
    s_base = pref;
  }
  __syncthreads();
  const int base = s_base + warp_pref[warp] + (ws - s);
#pragma unroll
  for (int i = 0; i < 4; i++) {
    int li = t * 4 + i;
    if (li < SCAN_CH) {
      int idx = b * SCAN_CH + li;
      int p = base + v[i];
      g_rowptr[idx] = p;
      g_cursor[idx] = p;
    }
  }
}

// Scan the degree histogram into bin offsets; reset hist for the next replay.
__global__ void binscan_kernel() {
  __shared__ int sh[NBINS];
  const int t = threadIdx.x;
  sh[t] = g_hist[t];
  g_hist[t] = 0;
  __syncthreads();
  for (int off = 1; off < NBINS; off <<= 1) {
    int u = (t >= off) ? sh[t - off] : 0;
    __syncthreads();
    sh[t] += u;
    __syncthreads();
  }
  g_binoff[t] = (t == 0) ? 0 : sh[t - 1];
}

// Hierarchical scatter: smem per-block histogram, ONE global atomic per
// nonzero bin per block (range reservation), then local scatter.
__global__ void __launch_bounds__(256) sort_scatter_kernel() {
  __shared__ int sh_cnt[NBINS];
  __shared__ int sh_base[NBINS];
  const int t = threadIdx.x;
  const int i = blockIdx.x * 256 + t;
  if (t < NBINS) sh_cnt[t] = 0;
  __syncthreads();
  int bin = 0, local = 0;
  if (i < NN) {
    int d1 = g_rowptr[i + 1] - g_rowptr[i];
    bin = min(d1, NBINS - 1);
    local = atomicAdd(&sh_cnt[bin], 1);
  }
  __syncthreads();
  if (t < NBINS && sh_cnt[t] > 0)
    sh_base[t] = atomicAdd(&g_binoff[t], sh_cnt[t]);
  __syncthreads();
  if (i < NN) g_order[sh_base[bin] + local] = i;
}

__global__ void fill_csr_kernel(const int* __restrict__ src,
                                const int* __restrict__ dst) {
  int t = blockIdx.x * 256 + threadIdx.x;
  if (t < EE) {
    int s = src[t], d = dst[t];
    int pos = atomicAdd(&g_cursor[d], 1);
    g_adj[pos] = make_int2(s, __float_as_int(g_dinv[s] * g_dinv[d]));
  } else if (t < NNZ) {
    int i = t - EE;
    int pos = atomicAdd(&g_cursor[i], 1);
    float di = g_dinv[i];
    g_adj[pos] = make_int2(i, __float_as_int(di * di));
  }
}

// ---------------- fp16-input aggregation (degree-sorted, pipelined) ----------
#define AGGH_ONE(cx, wy)                                                       \
  {                                                                            \
    uint4 xx = __ldg(reinterpret_cast<const uint4*>(Hin + (size_t)(cx) * D) + sub); \
    ull ww = pack2(__int_as_float(wy), __int_as_float(wy));                    \
    a0 = ffma2(h2ull(xx.x), ww, a0);                                           \
    a1 = ffma2(h2ull(xx.y), ww, a1);                                           \
    a2 = ffma2(h2ull(xx.z), ww, a2);                                           \
    a3 = ffma2(h2ull(xx.w), ww, a3);                                           \
  }
#define AGGH_Q(q)                                                              \
  {                                                                            \
    uint4 xa = __ldg(reinterpret_cast<const uint4*>(Hin + (size_t)(q).x * D) + sub); \
    uint4 xb = __ldg(reinterpret_cast<const uint4*>(Hin + (size_t)(q).z * D) + sub); \
    ull wa = pack2(__int_as_float((q).y), __int_as_float((q).y));              \
    ull wb = pack2(__int_as_float((q).w), __int_as_float((q).w));              \
    a0 = ffma2(h2ull(xa.x), wa, a0);                                           \
    a1 = ffma2(h2ull(xa.y), wa, a1);                                           \
    a2 = ffma2(h2ull(xa.z), wa, a2);                                           \
    a3 = ffma2(h2ull(xa.w), wa, a3);                                           \
    a0 = ffma2(h2ull(xb.x), wb, a0);                                           \
    a1 = ffma2(h2ull(xb.y), wb, a1);                                           \
    a2 = ffma2(h2ull(xb.z), wb, a2);                                           \
    a3 = ffma2(h2ull(xb.w), wb, a3);                                           \
  }

template <int D, bool RELU, bool BIAS, bool OUTH>
__global__ void __launch_bounds__(256) aggh_kernel(
    const __half* __restrict__ Hin, const float* __restrict__ bias,
    void* __restrict__ Hout) {
  constexpr int LANES = D / 8;
  const int slot = blockIdx.x * (256 / LANES) + threadIdx.x / LANES;
  const int node = __ldg(&g_order[slot]);   // degree-sorted: warp-mates match
  const int sub = threadIdx.x % LANES;
  int e = g_rowptr[node];
  const int end = g_rowptr[node + 1];

  ull a0 = 0ull, a1 = 0ull, a2 = 0ull, a3 = 0ull;
  if ((e & 1) && e < end) {
    int2 av = __ldg(&g_adj[e]);
    AGGH_ONE(av.x, av.y);
    e++;
  }
  // Software-pipelined 8-edge batches: prefetch batch k+1's adjacency
  // BEFORE issuing batch k's gathers -> adj latency overlaps gather latency.
  if (e + 8 <= end) {
    int4 q0 = __ldg(reinterpret_cast<const int4*>(g_adj + e));
    int4 q1 = __ldg(reinterpret_cast<const int4*>(g_adj + e + 2));
    int4 q2 = __ldg(reinterpret_cast<const int4*>(g_adj + e + 4));
    int4 q3 = __ldg(reinterpret_cast<const int4*>(g_adj + e + 6));
    while (e + 8 <= end) {
      const int en = e + 8;
      int4 n0, n1, n2, n3;
      if (en + 8 <= end) {
        n0 = __ldg(reinterpret_cast<const int4*>(g_adj + en));
        n1 = __ldg(reinterpret_cast<const int4*>(g_adj + en + 2));
        n2 = __ldg(reinterpret_cast<const int4*>(g_adj + en + 4));
        n3 = __ldg(reinterpret_cast<const int4*>(g_adj + en + 6));
      }
      AGGH_Q(q0);
      AGGH_Q(q1);
      AGGH_Q(q2);
      AGGH_Q(q3);
      q0 = n0; q1 = n1; q2 = n2; q3 = n3;
      e = en;
    }
  }
  for (; e + 2 <= end; e += 2) {
    int4 q = __ldg(reinterpret_cast<const int4*>(g_adj + e));
    AGGH_Q(q);
  }
  if (e < end) {
    int2 av = __ldg(&g_adj[e]);
    AGGH_ONE(av.x, av.y);
  }

  float2 r0 = u2f2(a0), r1 = u2f2(a1), r2 = u2f2(a2), r3 = u2f2(a3);
  if (BIAS) {
    float4 b0 = __ldg(reinterpret_cast<const float4*>(bias) + sub * 2);
    float4 b1 = __ldg(reinterpret_cast<const float4*>(bias) + sub * 2 + 1);
    r0.x += b0.x; r0.y += b0.y; r1.x += b0.z; r1.y += b0.w;
    r2.x += b1.x; r2.y += b1.y; r3.x += b1.z; r3.y += b1.w;
  }
  if (RELU) {
    r0.x = fmaxf(r0.x, 0.f); r0.y = fmaxf(r0.y, 0.f);
    r1.x = fmaxf(r1.x, 0.f); r1.y = fmaxf(r1.y, 0.f);
    r2.x = fmaxf(r2.x, 0.f); r2.y = fmaxf(r2.y, 0.f);
    r3.x = fmaxf(r3.x, 0.f); r3.y = fmaxf(r3.y, 0.f);
  }
  if (OUTH) {
    uint4 o;
    __half2 h0 = __floats2half2_rn(r0.x, r0.y);
    __half2 h1 = __floats2half2_rn(r1.x, r1.y);
    __half2 h2 = __floats2half2_rn(r2.x, r2.y);
    __half2 h3 = __floats2half2_rn(r3.x, r3.y);
    o.x = *reinterpret_cast<uint32_t*>(&h0);
    o.y = *reinterpret_cast<uint32_t*>(&h1);
    o.z = *reinterpret_cast<uint32_t*>(&h2);
    o.w = *reinterpret_cast<uint32_t*>(&h3);
    reinterpret_cast<uint4*>((__half*)Hout + (size_t)node * D)[sub] = o;
  } else {
    float4* orow = reinterpret_cast<float4*>((float*)Hout + (size_t)node * D);
    orow[sub * 2] = make_float4(r0.x, r0.y, r1.x, r1.y);
    orow[sub * 2 + 1] = make_float4(r2.x, r2.y, r3.x, r3.y);
  }
}
#undef AGGH_ONE
#undef AGGH_Q

// ---------------- fp32 FFMA GEMM (gemm1 / gemm5) -----------------------------
template <int K, int DOUT, bool RELU, bool BIAS, bool OUTH>
__global__ void __launch_bounds__(256) gemm_kernel(
    const float* __restrict__ A, const float* __restrict__ W,
    const float* __restrict__ bias, void* __restrict__ out) {
  constexpr int COLT = (DOUT < 64) ? DOUT : 64;
  constexpr int VPT = COLT / 32;
  constexpr int KS = K + 4;
  constexpr int R = 8;
  __shared__ __align__(16) float Ws[COLT * KS];
  __shared__ __align__(16) float As[64 * KS];

  const int col0 = blockIdx.y * COLT;
  const int row0 = blockIdx.x * 64;
  const int tid = threadIdx.x;

  constexpr int CHUNKS = 64 * (K / 4);
#pragma unroll 4
  for (int c = tid; c < CHUNKS; c += 256) {
    int row = c / (K / 4), col4 = c % (K / 4);
    cp_async16(s2u(&As[row * KS + col4 * 4]), A + (size_t)(row0 + row) * K + col4 * 4);
  }
  asm volatile("cp.async.commit_group;\n");

  for (int i = tid; i < COLT * K; i += 256) {
    int k = i / COLT, c = i - k * COLT;
    Ws[c * KS + k] = __ldg(&W[k * DOUT + col0 + c]);
  }
  asm volatile("cp.async.wait_group 0;\n");
  __syncthreads();

  const int lane = tid & 31;
  const int warp = tid >> 5;

  ull acc[R][VPT];
#pragma unroll
  for (int r = 0; r < R; r++)
#pragma unroll
    for (int v = 0; v < VPT; v++) acc[r][v] = 0ull;

#pragma unroll 2
  for (int k = 0; k < K; k += 4) {
    ull w01[VPT], w23[VPT];
#pragma unroll
    for (int v = 0; v < VPT; v++) {
      float4 wv = *reinterpret_cast<const float4*>(&Ws[(lane + 32 * v) * KS + k]);
      w01[v] = reinterpret_cast<ull*>(&wv)[0];
      w23[v] = reinterpret_cast<ull*>(&wv)[1];
    }
#pragma unroll
    for (int r = 0; r < R; r++) {
      float4 av = *reinterpret_cast<const float4*>(&As[(warp * R + r) * KS + k]);
      ull a01 = reinterpret_cast<ull*>(&av)[0];
      ull a23 = reinterpret_cast<ull*>(&av)[1];
#pragma unroll
      for (int v = 0; v < VPT; v++) {
        acc[r][v] = ffma2(a01, w01[v], acc[r][v]);
        acc[r][v] = ffma2(a23, w23[v], acc[r][v]);
      }
    }
  }

#pragma unroll
  for (int r = 0; r < R; r++) {
#pragma unroll
    for (int v = 0; v < VPT; v++) {
      float s = hsum2(acc[r][v]);
      int c = col0 + lane + 32 * v;
      if (BIAS) s += __ldg(&bias[c]);
      if (RELU) s = fmaxf(s, 0.0f);
      if (OUTH)
        ((__half*)out)[(size_t)(row0 + warp * R + r) * DOUT + c] = __float2half_rn(s);
      else
        ((float*)out)[(size_t)(row0 + warp * R + r) * DOUT + c] = s;
    }
  }
}

// ---------------- HMMA fp16 GEMM (interior layers) ---------------------------
template <int K, int DOUT, bool RELU, bool BIAS>
__global__ void __launch_bounds__(256) gemm_h_kernel(
    const __half* __restrict__ A, const float* __restrict__ W,
    const float* __restrict__ bias, __half* __restrict__ out) {
  constexpr int LDA = K + 8;
  constexpr int LDB = DOUT + 8;
  extern __shared__ __align__(16) __half smh[];
  __half* As = smh;               // [64][LDA]
  __half* Ws = smh + 64 * LDA;    // [K][LDB]

  const int tid = threadIdx.x;
  const int lane = tid & 31;
  const int warp = tid >> 5;
  const int row0 = blockIdx.x * 64;

  constexpr int RCH = K / 8;
#pragma unroll 4
  for (int c = tid; c < 64 * RCH; c += 256) {
    int r = c / RCH, cc = c % RCH;
    cp_async16(s2u(&As[r * LDA + cc * 8]), A + (size_t)(row0 + r) * K + cc * 8);
  }
  asm volatile("cp.async.commit_group;\n");

  for (int i = tid; i < K * DOUT; i += 256) {
    int k = i / DOUT, n = i - k * DOUT;
    Ws[k * LDB + n] = __float2half_rn(__ldg(&W[i]));
  }
  asm volatile("cp.async.wait_group 0;\n");
  __syncthreads();

  constexpr int SPAN = DOUT / 2;
  constexpr int NB = SPAN / 8;
  const int wr = warp & 3, wc = warp >> 2;
  const int r0 = wr * 16, n0 = wc * SPAN;

  float acc[NB][4];
#pragma unroll
  for (int nb = 0; nb < NB; nb++)
#pragma unroll
    for (int i = 0; i < 4; i++) acc[nb][i] = 0.0f;

  const uint32_t a_base = s2u(&As[(r0 + (lane & 15)) * LDA + (lane >> 4) * 8]);
  const int bt_row = ((lane >> 3) & 1) * 8 + (lane & 7);
  const int bt_col = (lane >> 4) * 8;
  const uint32_t b_base = s2u(&Ws[bt_row * LDB + n0 + bt_col]);

#pragma unroll
  for (int ks = 0; ks < K / 16; ks++) {
    uint32_t a0, a1, a2, a3;
    ldsm_x4(a0, a1, a2, a3, a_base + ks * 32);
#pragma unroll
    for (int nb = 0; nb < NB; nb += 2) {
      uint32_t b0, b1, b2, b3;
      ldsm_x4_t(b0, b1, b2, b3,
                b_base + (uint32_t)(ks * 16 * LDB + nb * 8) * 2);
      mma16816(acc[nb], a0, a1, a2, a3, b0, b1);
      mma16816(acc[nb + 1], a0, a1, a2, a3, b2, b3);
    }
  }

  const int orow = row0 + r0 + (lane >> 2);
#pragma unroll
  for (int nb = 0; nb < NB; nb++) {
    int col = n0 + nb * 8 + (lane & 3) * 2;
    float v0 = acc[nb][0], v1 = acc[nb][1], v2 = acc[nb][2], v3 = acc[nb][3];
    if (BIAS) {
      float b0 = __ldg(&bias[col]), b1 = __ldg(&bias[col + 1]);
      v0 += b0; v1 += b1; v2 += b0; v3 += b1;
    }
    if (RELU) {
      v0 = fmaxf(v0, 0.f); v1 = fmaxf(v1, 0.f);
      v2 = fmaxf(v2, 0.f); v3 = fmaxf(v3, 0.f);
    }
    __half2 h01 = __floats2half2_rn(v0, v1);
    __half2 h23 = __floats2half2_rn(v2, v3);
    *reinterpret_cast<__half2*>(&out[(size_t)orow * DOUT + col]) = h01;
    *reinterpret_cast<__half2*>(&out[(size_t)(orow + 8) * DOUT + col]) = h23;
  }
}

// ---------------- launch ------------------------------------------------------
extern "C" void kernel_launch(void* const* d_in, const int* in_sizes, int n_in,
                              void* d_out, int out_size) {
  (void)in_sizes; (void)n_in; (void)out_size;
  const float* x  = (const float*)d_in[0];
  const int*   ei = (const int*)d_in[1];
  const int* src = ei;
  const int* dst = ei + EE;
  const float* W1 = (const float*)d_in[3];
  const float* b1 = (const float*)d_in[4];
  const float* W2 = (const float*)d_in[5];
  const float* b2 = (const float*)d_in[6];
  const float* W3 = (const float*)d_in[7];
  const float* b3 = (const float*)d_in[8];
  const float* W4 = (const float*)d_in[9];
  const float* b4 = (const float*)d_in[10];
  const float* Wl = (const float*)d_in[11];
  const float* bl = (const float*)d_in[12];
  float* out = (float*)d_out;

  float* buf0;
  __half *hbuf0, *hbuf1;
  cudaGetSymbolAddress((void**)&buf0, g_buf0);
  cudaGetSymbolAddress((void**)&hbuf0, g_hbuf0);
  cudaGetSymbolAddress((void**)&hbuf1, g_hbuf1);

  const int SM23 = (64 * (64 + 8) + 64 * (128 + 8)) * 2;
  const int SM33 = (64 * (128 + 8) + 128 * (128 + 8)) * 2;
  const int SM34 = (64 * (128 + 8) + 128 * (64 + 8)) * 2;

  static cudaStream_t s_prep = nullptr;
  static cudaEvent_t ev_fork = nullptr, ev_join = nullptr;
  if (s_prep == nullptr) {
    cudaStreamCreateWithFlags(&s_prep, cudaStreamNonBlocking);
    cudaEventCreateWithFlags(&ev_fork, cudaEventDisableTiming);
    cudaEventCreateWithFlags(&ev_join, cudaEventDisableTiming);
    cudaFuncSetAttribute(gemm_h_kernel<128, 128, false, false>,
                         cudaFuncAttributeMaxDynamicSharedMemorySize, SM33);
    cudaFuncSetAttribute(gemm_h_kernel<64, 128, true, true>,
                         cudaFuncAttributeMaxDynamicSharedMemorySize, SM23);
    cudaFuncSetAttribute(gemm_h_kernel<128, 64, false, false>,
                         cudaFuncAttributeMaxDynamicSharedMemorySize, SM34);
  }

  // ---- fork: CSR prep + degree sort on s_prep, overlapped with gemm1.
  cudaEventRecord(ev_fork, 0);
  cudaStreamWaitEvent(s_prep, ev_fork, 0);

  count_deg_kernel<<<(EE + 255) / 256, 256, 0, s_prep>>>(dst);
  scan_fused_kernel<<<NSCAN_BLK, 256, 0, s_prep>>>();
  binscan_kernel<<<1, NBINS, 0, s_prep>>>();
  sort_scatter_kernel<<<(NN + 255) / 256, 256, 0, s_prep>>>();
  fill_csr_kernel<<<(NNZ + 255) / 256, 256, 0, s_prep>>>(src, dst);
  cudaEventRecord(ev_join, s_prep);

  const int GEMM_BLOCKS = NN / 64;      // 625
  const int AGGH64_BLOCKS = NN / 32;    // 1250 (8 lanes/node)
  const int AGGH128_BLOCKS = NN / 16;   // 2500 (16 lanes/node)

  // L1 GEMM overlaps prep: t = x @ W1 -> fp16
  gemm_kernel<128, 64, false, false, true>
      <<<dim3(GEMM_BLOCKS, 1), 256>>>(x, W1, nullptr, hbuf0);

  cudaStreamWaitEvent(0, ev_join, 0);  // join: aggs need CSR + order

  // h1 = relu(agg(t) + b1) -> fp16
  aggh_kernel<64, true, true, true><<<AGGH64_BLOCKS, 256>>>(hbuf0, b1, hbuf1);
  // a = agg(h1) -> fp16
  aggh_kernel<64, false, false, true><<<AGGH64_BLOCKS, 256>>>(hbuf1, nullptr, hbuf0);
  // h2 = relu(a @ W2 + b2) -> fp16   [HMMA]
  gemm_h_kernel<64, 128, true, true>
      <<<GEMM_BLOCKS, 256, SM23>>>(hbuf0, W2, b2, hbuf1);
  // t3 = h2 @ W3 -> fp16             [HMMA]
  gemm_h_kernel<128, 128, false, false>
      <<<GEMM_BLOCKS, 256, SM33>>>(hbuf1, W3, nullptr, hbuf0);
  // h3 = relu(agg(t3) + b3) -> fp16
  aggh_kernel<128, true, true, true><<<AGGH128_BLOCKS, 256>>>(hbuf0, b3, hbuf1);
  // t4 = h3 @ W4 -> fp16             [HMMA]
  gemm_h_kernel<128, 64, false, false>
      <<<GEMM_BLOCKS, 256, SM34>>>(hbuf1, W4, nullptr, hbuf0);
  // h4 = relu(agg(t4) + b4) -> fp32
  aggh_kernel<64, true, true, false><<<AGGH64_BLOCKS, 256>>>(hbuf0, b4, buf0);
  // Head: out = h4 @ Wl + bl -> fp32 [FFMA]
  gemm_kernel<64, 32, false, true, false>
      <<<dim3(GEMM_BLOCKS, 1), 256>>>(buf0, Wl, bl, out);
}